// round 8
// baseline (speedup 1.0000x reference)
#include <cuda_runtime.h>
#include <cuda_fp16.h>
#include <math.h>
#include <stdint.h>

#define DIM    256
#define INNER  512
#define HEADS  8
#define DHEAD  64
#define NTOK   49
#define NPIX   3136
#define BATCH  16
#define NWIN   64
#define EPS    1e-5f

// Scratch (allocation-free: __device__ globals) — intermediates in fp16
__device__ __half g_y[3][BATCH * DIM * NPIX];      // dwconv+BN outputs: [b][c][pix]
__device__ __half g_qkv[3][BATCH * INNER * NPIX];  // projected: [b][c][pix]
__device__ __half g_att[BATCH * INNER * NPIX];     // attention out: [b][ci][y][x]
__device__ float  g_bias[HEADS * NTOK * NTOK];     // rel-pos bias: [h][i][j]

// ---------------------------------------------------------------------------
// fp16 MMA m16n8k16, fp32 accum
// ---------------------------------------------------------------------------
__device__ __forceinline__ void mma_f16(float c[4], const uint32_t a[4], const uint32_t b[2]) {
    asm volatile(
        "mma.sync.aligned.m16n8k16.row.col.f32.f16.f16.f32 "
        "{%0,%1,%2,%3}, {%4,%5,%6,%7}, {%8,%9}, {%0,%1,%2,%3};\n"
        : "+f"(c[0]), "+f"(c[1]), "+f"(c[2]), "+f"(c[3])
        : "r"(a[0]), "r"(a[1]), "r"(a[2]), "r"(a[3]), "r"(b[0]), "r"(b[1]));
}

// ---------------------------------------------------------------------------
// Kernel C: precompute relative position bias table [h][i][j]
// ---------------------------------------------------------------------------
__global__ void bias_kernel(const float* __restrict__ pos) {
    int idx = blockIdx.x * 256 + threadIdx.x;
    if (idx >= HEADS * NTOK * NTOK) return;
    int h = idx / (NTOK * NTOK);
    int r = idx % (NTOK * NTOK);
    int i = r / NTOK, j = r % NTOK;
    int xi = i / 7, yi = i % 7, xj = j / 7, yj = j % 7;
    int rel = (xj - xi + 6) * 13 + (yj - yi + 6);
    g_bias[idx] = __ldg(pos + rel * HEADS + h);
}

// ---------------------------------------------------------------------------
// Kernel A: depthwise 3x3 conv + BN, 4 pixels/thread, fp16 output
// ---------------------------------------------------------------------------
__global__ void __launch_bounds__(256) dwbn_kernel(
    const float* __restrict__ x,
    const float* __restrict__ dwq, const float* __restrict__ gq, const float* __restrict__ bq,
    const float* __restrict__ mq,  const float* __restrict__ vq,
    const float* __restrict__ dwk, const float* __restrict__ gk, const float* __restrict__ bk,
    const float* __restrict__ mk,  const float* __restrict__ vk,
    const float* __restrict__ dwv, const float* __restrict__ gv, const float* __restrict__ bv,
    const float* __restrict__ mv,  const float* __restrict__ vv)
{
    int pg = blockIdx.x * 256 + threadIdx.x;
    if (pg >= NPIX / 4) return;
    int p0 = pg * 4;
    int bc = blockIdx.y;
    int c  = bc & (DIM - 1);
    const float* xp = x + (size_t)bc * NPIX;
    int y0 = p0 / 56, x0 = p0 % 56;

    float t[3][6];
#pragma unroll
    for (int dy = 0; dy < 3; dy++) {
        int yy = y0 + dy - 1;
        bool rowOk = (yy >= 0 && yy < 56);
        const float* rp = xp + yy * 56;
        t[dy][0] = (rowOk && x0 > 0) ? __ldg(rp + x0 - 1) : 0.f;
        if (rowOk) {
            float4 mid = *(const float4*)(rp + x0);
            t[dy][1] = mid.x; t[dy][2] = mid.y; t[dy][3] = mid.z; t[dy][4] = mid.w;
        } else {
            t[dy][1] = t[dy][2] = t[dy][3] = t[dy][4] = 0.f;
        }
        t[dy][5] = (rowOk && x0 + 4 < 56) ? __ldg(rp + x0 + 4) : 0.f;
    }

    const float* DW[3] = {dwq, dwk, dwv};
    const float* GG[3] = {gq, gk, gv};
    const float* BB[3] = {bq, bk, bv};
    const float* MM[3] = {mq, mk, mv};
    const float* VV[3] = {vq, vk, vv};

#pragma unroll
    for (int pr = 0; pr < 3; pr++) {
        const float* wp = DW[pr] + c * 9;
        float w[9];
#pragma unroll
        for (int j = 0; j < 9; j++) w[j] = __ldg(wp + j);

        float o[4] = {0.f, 0.f, 0.f, 0.f};
#pragma unroll
        for (int dy = 0; dy < 3; dy++)
#pragma unroll
            for (int dx = 0; dx < 3; dx++) {
                float ww = w[dy * 3 + dx];
#pragma unroll
                for (int i = 0; i < 4; i++)
                    o[i] += ww * t[dy][i + dx];
            }

        float sc = __ldg(GG[pr] + c) * rsqrtf(__ldg(VV[pr] + c) + EPS);
        float sh = __ldg(BB[pr] + c) - __ldg(MM[pr] + c) * sc;
        __half2 h01 = __floats2half2_rn(o[0] * sc + sh, o[1] * sc + sh);
        __half2 h23 = __floats2half2_rn(o[2] * sc + sh, o[3] * sc + sh);
        uint2 pk;
        pk.x = *reinterpret_cast<uint32_t*>(&h01);
        pk.y = *reinterpret_cast<uint32_t*>(&h23);
        *reinterpret_cast<uint2*>(&g_y[pr][(size_t)bc * NPIX + p0]) = pk;
    }
}

// ---------------------------------------------------------------------------
// fp16 GEMM core: D[128,128] = A[128,K](fp32) * B[K,128](fp16)
// m16n8k16, BK=16, double-buffered. A smem [m][k] str 24h; B smem [n][k] str 24h.
// 8 warps: wm=(warp&1)*64, wn=(warp>>1)*32; warp tile 64x32.
// ---------------------------------------------------------------------------
template<int KDIM, bool OUTHALF>
__device__ __forceinline__ void h_gemm(
    const float* __restrict__ A, int m0,
    const __half* __restrict__ B, int n0,
    void* __restrict__ OutBase,
    const float* __restrict__ biasv)
{
    __shared__ __align__(16) __half As[2][128 * 24];
    __shared__ __align__(16) __half Bs[2][128 * 24];

    int tid = threadIdx.x, lane = tid & 31, warp = tid >> 5;
    int wm = (warp & 1) * 64, wn = (warp >> 1) * 32;
    int q = lane & 3, rb = lane >> 2;

    int am = tid >> 1, kq = (tid & 1) * 8;    // A staging: row, k-octet
    int bk = tid >> 4, bn0 = (tid & 15) * 8;  // B staging: k-row, n-octet
    bool bOk = (n0 + bn0) < NPIX;

    float acc[4][4][4];
#pragma unroll
    for (int mt = 0; mt < 4; mt++)
#pragma unroll
        for (int nt = 0; nt < 4; nt++)
#pragma unroll
            for (int i = 0; i < 4; i++) acc[mt][nt][i] = 0.f;

    // prologue: stage 0
    {
        float4 a0 = *(const float4*)(A + (size_t)(m0 + am) * KDIM + kq);
        float4 a1 = *(const float4*)(A + (size_t)(m0 + am) * KDIM + kq + 4);
        __half2 h0 = __floats2half2_rn(a0.x, a0.y);
        __half2 h1 = __floats2half2_rn(a0.z, a0.w);
        __half2 h2 = __floats2half2_rn(a1.x, a1.y);
        __half2 h3 = __floats2half2_rn(a1.z, a1.w);
        uint4 u;
        u.x = *reinterpret_cast<uint32_t*>(&h0);
        u.y = *reinterpret_cast<uint32_t*>(&h1);
        u.z = *reinterpret_cast<uint32_t*>(&h2);
        u.w = *reinterpret_cast<uint32_t*>(&h3);
        *reinterpret_cast<uint4*>(&As[0][am * 24 + kq]) = u;

        uint4 pb = make_uint4(0u, 0u, 0u, 0u);
        if (bOk) pb = *(const uint4*)(B + (size_t)bk * NPIX + n0 + bn0);
        __half hv[8];
        *reinterpret_cast<uint4*>(hv) = pb;
#pragma unroll
        for (int e = 0; e < 8; e++) Bs[0][(bn0 + e) * 24 + bk] = hv[e];
    }
    __syncthreads();

    const int NS = KDIM / 16;
    for (int s = 0; s < NS; s++) {
        float4 pa0, pa1;
        uint4 pb = make_uint4(0u, 0u, 0u, 0u);
        bool more = (s + 1) < NS;
        if (more) {
            int k0 = (s + 1) * 16;
            pa0 = *(const float4*)(A + (size_t)(m0 + am) * KDIM + k0 + kq);
            pa1 = *(const float4*)(A + (size_t)(m0 + am) * KDIM + k0 + kq + 4);
            if (bOk) pb = *(const uint4*)(B + (size_t)(k0 + bk) * NPIX + n0 + bn0);
        }

        int buf = s & 1;
        const uint32_t* Aw = (const uint32_t*)As[buf];
        const uint32_t* Bw = (const uint32_t*)Bs[buf];
        uint32_t af[4][4], bf[4][2];
#pragma unroll
        for (int mt = 0; mt < 4; mt++) {
            int r = wm + mt * 16 + rb;
            af[mt][0] = Aw[r * 12 + q];
            af[mt][1] = Aw[(r + 8) * 12 + q];
            af[mt][2] = Aw[r * 12 + 4 + q];
            af[mt][3] = Aw[(r + 8) * 12 + 4 + q];
        }
#pragma unroll
        for (int nt = 0; nt < 4; nt++) {
            int n = wn + nt * 8 + rb;
            bf[nt][0] = Bw[n * 12 + q];
            bf[nt][1] = Bw[n * 12 + 4 + q];
        }
#pragma unroll
        for (int mt = 0; mt < 4; mt++)
#pragma unroll
            for (int nt = 0; nt < 4; nt++)
                mma_f16(acc[mt][nt], af[mt], bf[nt]);

        if (more) {
            int nbuf = (s + 1) & 1;
            __half2 h0 = __floats2half2_rn(pa0.x, pa0.y);
            __half2 h1 = __floats2half2_rn(pa0.z, pa0.w);
            __half2 h2 = __floats2half2_rn(pa1.x, pa1.y);
            __half2 h3 = __floats2half2_rn(pa1.z, pa1.w);
            uint4 u;
            u.x = *reinterpret_cast<uint32_t*>(&h0);
            u.y = *reinterpret_cast<uint32_t*>(&h1);
            u.z = *reinterpret_cast<uint32_t*>(&h2);
            u.w = *reinterpret_cast<uint32_t*>(&h3);
            *reinterpret_cast<uint4*>(&As[nbuf][am * 24 + kq]) = u;
            __half hv[8];
            *reinterpret_cast<uint4*>(hv) = pb;
#pragma unroll
            for (int e = 0; e < 8; e++) Bs[nbuf][(bn0 + e) * 24 + bk] = hv[e];
        }
        __syncthreads();
    }

    // epilogue
#pragma unroll
    for (int mt = 0; mt < 4; mt++) {
#pragma unroll
        for (int rr = 0; rr < 2; rr++) {
            int m = m0 + wm + mt * 16 + rb + rr * 8;
            float bias = biasv ? __ldg(biasv + m) : 0.f;
#pragma unroll
            for (int nt = 0; nt < 4; nt++) {
                int n = n0 + wn + nt * 8 + q * 2;
                if (n < NPIX) {
                    if constexpr (OUTHALF) {
                        __half* Out = (__half*)OutBase;
                        __half2 hv = __floats2half2_rn(acc[mt][nt][rr * 2 + 0],
                                                       acc[mt][nt][rr * 2 + 1]);
                        *reinterpret_cast<__half2*>(&Out[(size_t)m * NPIX + n]) = hv;
                    } else {
                        float* Out = (float*)OutBase;
                        float2 v;
                        v.x = acc[mt][nt][rr * 2 + 0] + bias;
                        v.y = acc[mt][nt][rr * 2 + 1] + bias;
                        *(float2*)&Out[(size_t)m * NPIX + n] = v;
                    }
                }
            }
        }
    }
}

// Kernel B: proj GEMM (fp16 out, no bias)
__global__ void __launch_bounds__(256, 2) proj_gemm_h(
    const float* __restrict__ pw0, const float* __restrict__ pw1,
    const float* __restrict__ pw2)
{
    int mb = blockIdx.x;                 // 0..3 (fastest -> L2 B reuse)
    int nb = blockIdx.y;                 // 0..24
    int bz = blockIdx.z;                 // b*3 + proj
    int pr = bz % 3, b = bz / 3;
    const float* A = (pr == 0) ? pw0 : ((pr == 1) ? pw1 : pw2);
    const __half* B = g_y[pr] + (size_t)b * DIM * NPIX;
    __half* Out = g_qkv[pr] + (size_t)b * INNER * NPIX;
    h_gemm<DIM, true>(A, mb * 128, B, nb * 128, Out, nullptr);
}

// Kernel E: out GEMM (fp32 out + bias)
__global__ void __launch_bounds__(256, 2) out_gemm_h(
    const float* __restrict__ A, const float* __restrict__ ob,
    float* __restrict__ out)
{
    int mb = blockIdx.x;                 // 0..1
    int nb = blockIdx.y;                 // 0..24
    int b  = blockIdx.z;                 // 0..15
    const __half* B = g_att + (size_t)b * INNER * NPIX;
    float* Out = out + (size_t)b * DIM * NPIX;
    h_gemm<INNER, false>(A, mb * 128, B, nb * 128, Out, ob);
}

// ---------------------------------------------------------------------------
// Kernel D: fp16 windowed attention. One CTA per (b, h, w).
// QK: A=Q[t][d] s72h, B=K[t][d] s72h, K=64 (4 k16). dots fp32 [49][60].
// softmax quad-per-row -> attnB fp16 [i][j] s72h (aliases qs), rows/cols>=49 zero.
// AV: A=V[d][t] s72h (cols 49..63 zero), B=attnB, K=64. smem 38.3KB.
// ---------------------------------------------------------------------------
__global__ void __launch_bounds__(256) attn_h() {
    __shared__ __align__(16) __half qs[64 * 72];   // Q; later attnB
    __shared__ __align__(16) __half ks[56 * 72];
    __shared__ __align__(16) __half vs[64 * 72];
    __shared__ __align__(16) float dots[49 * 60];

    int w = blockIdx.x, h = blockIdx.y, b = blockIdx.z;
    int tid = threadIdx.x, lane = tid & 31, warp = tid >> 5;
    int q = lane & 3, rb = lane >> 2;
    int nh = w >> 3, nw2 = w & 7;
    int px0 = (nh * 7) * 56 + nw2 * 7;

    size_t cbase = ((size_t)b * INNER + h * DHEAD) * NPIX;
    const __half* qg = g_qkv[0] + cbase;
    const __half* kg = g_qkv[1] + cbase;
    const __half* vg = g_qkv[2] + cbase;

    for (int idx = tid; idx < DHEAD * NTOK; idx += 256) {
        int d = idx / NTOK, t = idx - d * NTOK;
        int poff = px0 + (t / 7) * 56 + (t % 7);
        size_t g = (size_t)d * NPIX + poff;
        qs[t * 72 + d] = qg[g];
        ks[t * 72 + d] = kg[g];
        vs[d * 72 + t] = vg[g];
    }
    // zero V pad cols t=49..63 (AV K-pad must contribute exactly 0)
    for (int idx = tid; idx < DHEAD * 15; idx += 256) {
        int d = idx / 15, t = NTOK + idx % 15;
        reinterpret_cast<uint16_t*>(vs)[d * 72 + t] = 0;
    }
    __syncthreads();

    int wm = (warp >> 1) * 16;          // m16 tile (i for QK, d for AV)
    int wn = (warp & 1) * 32;           // n half
    int ntmax = (warp & 1) ? 3 : 4;     // N=56 for QK

    const uint32_t* qsw = (const uint32_t*)qs;
    const uint32_t* ksw = (const uint32_t*)ks;

    // ---- QK^T (garbage in qs rows>=49 / ks rows>=49 stays in unpicked elements)
    float acc[4][4];
#pragma unroll
    for (int nt = 0; nt < 4; nt++)
#pragma unroll
        for (int i = 0; i < 4; i++) acc[nt][i] = 0.f;

#pragma unroll
    for (int kk = 0; kk < 4; kk++) {
        int kw = kk * 8;
        int r = wm + rb;
        uint32_t af[4];
        af[0] = qsw[r * 36 + kw + q];
        af[1] = qsw[(r + 8) * 36 + kw + q];
        af[2] = qsw[r * 36 + kw + 4 + q];
        af[3] = qsw[(r + 8) * 36 + kw + 4 + q];
#pragma unroll
        for (int nt = 0; nt < 4; nt++) {
            if (nt < ntmax) {
                int n = wn + nt * 8 + rb;
                uint32_t bf[2];
                bf[0] = ksw[n * 36 + kw + q];
                bf[1] = ksw[n * 36 + kw + 4 + q];
                mma_f16(acc[nt], af, bf);
            }
        }
    }

    // ---- dots (+bias), fp32, separate buffer (no alias yet)
    const float* bptr = g_bias + h * NTOK * NTOK;
#pragma unroll
    for (int nt = 0; nt < 4; nt++) {
        if (nt < ntmax) {
#pragma unroll
            for (int rr = 0; rr < 2; rr++) {
                int i = wm + rb + rr * 8;
                if (i < NTOK) {
                    int j = wn + nt * 8 + q * 2;
                    if (j < NTOK)
                        dots[i * 60 + j] = acc[nt][rr * 2] * 0.125f + __ldg(bptr + i * NTOK + j);
                    if (j + 1 < NTOK)
                        dots[i * 60 + j + 1] = acc[nt][rr * 2 + 1] * 0.125f + __ldg(bptr + i * NTOK + j + 1);
                }
            }
        }
    }
    __syncthreads();   // QK reads of qs done; dots visible

    // ---- softmax: quad per row; writes attnB (alias qs), ALL 64 rows x 64 cols
    {
        int i = warp * 8 + rb;           // 0..63
        bool rowOk = (i < NTOK);
        float va[16];
        float mx = -1e30f;
#pragma unroll
        for (int it = 0; it < 8; it++) {
            int j0 = it * 8 + q * 2;
            float vx = (rowOk && j0 < NTOK) ? dots[i * 60 + j0] : -1e30f;
            float vy = (rowOk && j0 + 1 < NTOK) ? dots[i * 60 + j0 + 1] : -1e30f;
            va[it * 2] = vx; va[it * 2 + 1] = vy;
            mx = fmaxf(mx, fmaxf(vx, vy));
        }
        mx = fmaxf(mx, __shfl_xor_sync(0xffffffffu, mx, 1));
        mx = fmaxf(mx, __shfl_xor_sync(0xffffffffu, mx, 2));
        float s = 0.f;
#pragma unroll
        for (int it = 0; it < 16; it++) {
            float e = __expf(va[it] - mx);   // pad lanes: exp(-huge)=0
            va[it] = e;
            s += e;
        }
        s += __shfl_xor_sync(0xffffffffu, s, 1);
        s += __shfl_xor_sync(0xffffffffu, s, 2);
        float inv = 1.f / s;
#pragma unroll
        for (int it = 0; it < 8; it++) {
            int j0 = it * 8 + q * 2;
            __half2 hv = rowOk ? __floats2half2_rn(va[it * 2] * inv, va[it * 2 + 1] * inv)
                               : __floats2half2_rn(0.f, 0.f);
            *reinterpret_cast<__half2*>(&qs[i * 72 + j0]) = hv;
        }
    }
    __syncthreads();

    // ---- AV: outT[d][i] = sum_j V[d][j] * attnB[i][j], K=64 (pads are 0*0)
    const uint32_t* vsw = (const uint32_t*)vs;
    const uint32_t* aBw = (const uint32_t*)qs;
    float acc2[4][4];
#pragma unroll
    for (int nt = 0; nt < 4; nt++)
#pragma unroll
        for (int i = 0; i < 4; i++) acc2[nt][i] = 0.f;

#pragma unroll
    for (int kk = 0; kk < 4; kk++) {
        int kw = kk * 8;
        int r = wm + rb;
        uint32_t af[4];
        af[0] = vsw[r * 36 + kw + q];
        af[1] = vsw[(r + 8) * 36 + kw + q];
        af[2] = vsw[r * 36 + kw + 4 + q];
        af[3] = vsw[(r + 8) * 36 + kw + 4 + q];
#pragma unroll
        for (int nt = 0; nt < 4; nt++) {
            int n = wn + nt * 8 + rb;
            uint32_t bf[2];
            bf[0] = aBw[n * 36 + kw + q];
            bf[1] = aBw[n * 36 + kw + 4 + q];
            mma_f16(acc2[nt], af, bf);
        }
    }

    // ---- store (un-window), fp16: [b][ci][y][x]
    __half* outp = g_att + (size_t)b * INNER * NPIX + (size_t)h * DHEAD * NPIX;
#pragma unroll
    for (int nt = 0; nt < 4; nt++) {
#pragma unroll
        for (int c = 0; c < 2; c++) {
            int i = wn + nt * 8 + q * 2 + c;
            if (i < NTOK) {
                int poff = px0 + (i / 7) * 56 + (i % 7);
#pragma unroll
                for (int rr = 0; rr < 2; rr++) {
                    int d = wm + rb + rr * 8;
                    outp[(size_t)d * NPIX + poff] = __float2half_rn(acc2[nt][rr * 2 + c]);
                }
            }
        }
    }
}

// ---------------------------------------------------------------------------
extern "C" void kernel_launch(void* const* d_in, const int* in_sizes, int n_in,
                              void* d_out, int out_size) {
    const float* x   = (const float*)d_in[0];
    const float* qdw = (const float*)d_in[1];
    const float* qg  = (const float*)d_in[2];
    const float* qb  = (const float*)d_in[3];
    const float* qm  = (const float*)d_in[4];
    const float* qv  = (const float*)d_in[5];
    const float* qpw = (const float*)d_in[6];
    const float* kdw = (const float*)d_in[7];
    const float* kg  = (const float*)d_in[8];
    const float* kb  = (const float*)d_in[9];
    const float* km  = (const float*)d_in[10];
    const float* kv  = (const float*)d_in[11];
    const float* kpw = (const float*)d_in[12];
    const float* vdw = (const float*)d_in[13];
    const float* vg  = (const float*)d_in[14];
    const float* vb  = (const float*)d_in[15];
    const float* vm  = (const float*)d_in[16];
    const float* vv  = (const float*)d_in[17];
    const float* vpw = (const float*)d_in[18];
    const float* pos = (const float*)d_in[19];
    const float* ow  = (const float*)d_in[20];
    const float* obias = (const float*)d_in[21];
    float* out = (float*)d_out;

    bias_kernel<<<(HEADS * NTOK * NTOK + 255) / 256, 256>>>(pos);

    dwbn_kernel<<<dim3((NPIX / 4 + 255) / 256, BATCH * DIM), 256>>>(
        x, qdw, qg, qb, qm, qv, kdw, kg, kb, km, kv, vdw, vg, vb, vm, vv);

    proj_gemm_h<<<dim3(4, 25, BATCH * 3), 256>>>(qpw, kpw, vpw);

    attn_h<<<dim3(NWIN, HEADS, BATCH), 256>>>();

    out_gemm_h<<<dim3(2, 25, BATCH), 256>>>(ow, obias, out);
}

// round 9
// speedup vs baseline: 1.4076x; 1.4076x over previous
#include <cuda_runtime.h>
#include <math.h>
#include <stdint.h>

#define DIM    256
#define INNER  512
#define HEADS  8
#define DHEAD  64
#define NTOK   49
#define NPIX   3136
#define BATCH  16
#define NWIN   64
#define EPS    1e-5f

// Scratch (allocation-free: __device__ globals)
// g_y:   plain [b][c][pix]           (pix = y*56+x)
// g_qkv: windowed [b][c][pix']       (pix' = w*49 + t)
// g_att: windowed [b][c][pix']
__device__ float g_y[3][BATCH * DIM * NPIX];
__device__ float g_qkv[3][BATCH * INNER * NPIX];
__device__ float g_att[BATCH * INNER * NPIX];
__device__ float g_bias[HEADS * NTOK * NTOK];

// ---------------------------------------------------------------------------
// helpers
// ---------------------------------------------------------------------------
__device__ __forceinline__ uint32_t f2tf(float f) {
    uint32_t u;
    asm("cvt.rna.tf32.f32 %0, %1;" : "=r"(u) : "f"(f));
    return u;
}

__device__ __forceinline__ void mma_tf32(float c[4], const uint32_t a[4], const uint32_t b[2]) {
    asm volatile(
        "mma.sync.aligned.m16n8k8.row.col.f32.tf32.tf32.f32 "
        "{%0,%1,%2,%3}, {%4,%5,%6,%7}, {%8,%9}, {%0,%1,%2,%3};\n"
        : "+f"(c[0]), "+f"(c[1]), "+f"(c[2]), "+f"(c[3])
        : "r"(a[0]), "r"(a[1]), "r"(a[2]), "r"(a[3]), "r"(b[0]), "r"(b[1]));
}

// windowed token index -> plain pixel offset
__device__ __forceinline__ int pixoff(int n) {
    int w = n / 49, t = n - w * 49;
    int ty = t / 7, tx = t - ty * 7;
    return ((w >> 3) * 7 + ty) * 56 + (w & 7) * 7 + tx;
}

// ---------------------------------------------------------------------------
// Kernel C: precompute relative position bias table [h][i][j]
// ---------------------------------------------------------------------------
__global__ void bias_kernel(const float* __restrict__ pos) {
    int idx = blockIdx.x * 256 + threadIdx.x;
    if (idx >= HEADS * NTOK * NTOK) return;
    int h = idx / (NTOK * NTOK);
    int r = idx % (NTOK * NTOK);
    int i = r / NTOK, j = r % NTOK;
    int xi = i / 7, yi = i % 7, xj = j / 7, yj = j % 7;
    int rel = (xj - xi + 6) * 13 + (yj - yi + 6);
    g_bias[idx] = __ldg(pos + rel * HEADS + h);
}

// ---------------------------------------------------------------------------
// Kernel A: depthwise 3x3 conv + BN, 4 row-aligned pixels per thread
// ---------------------------------------------------------------------------
__global__ void __launch_bounds__(256) dwbn_kernel(
    const float* __restrict__ x,
    const float* __restrict__ dwq, const float* __restrict__ gq, const float* __restrict__ bq,
    const float* __restrict__ mq,  const float* __restrict__ vq,
    const float* __restrict__ dwk, const float* __restrict__ gk, const float* __restrict__ bk,
    const float* __restrict__ mk,  const float* __restrict__ vk,
    const float* __restrict__ dwv, const float* __restrict__ gv, const float* __restrict__ bv,
    const float* __restrict__ mv,  const float* __restrict__ vv)
{
    int pg = blockIdx.x * 256 + threadIdx.x;
    if (pg >= NPIX / 4) return;
    int p0 = pg * 4;
    int bc = blockIdx.y;
    int c  = bc & (DIM - 1);
    const float* xp = x + (size_t)bc * NPIX;
    int y0 = p0 / 56, x0 = p0 % 56;

    float t[3][6];
#pragma unroll
    for (int dy = 0; dy < 3; dy++) {
        int yy = y0 + dy - 1;
        bool rowOk = (yy >= 0 && yy < 56);
        const float* rp = xp + yy * 56;
        t[dy][0] = (rowOk && x0 > 0) ? __ldg(rp + x0 - 1) : 0.f;
        if (rowOk) {
            float4 mid = *(const float4*)(rp + x0);
            t[dy][1] = mid.x; t[dy][2] = mid.y; t[dy][3] = mid.z; t[dy][4] = mid.w;
        } else {
            t[dy][1] = t[dy][2] = t[dy][3] = t[dy][4] = 0.f;
        }
        t[dy][5] = (rowOk && x0 + 4 < 56) ? __ldg(rp + x0 + 4) : 0.f;
    }

    const float* DW[3] = {dwq, dwk, dwv};
    const float* GG[3] = {gq, gk, gv};
    const float* BB[3] = {bq, bk, bv};
    const float* MM[3] = {mq, mk, mv};
    const float* VV[3] = {vq, vk, vv};

#pragma unroll
    for (int pr = 0; pr < 3; pr++) {
        const float* wp = DW[pr] + c * 9;
        float w[9];
#pragma unroll
        for (int j = 0; j < 9; j++) w[j] = __ldg(wp + j);

        float o[4] = {0.f, 0.f, 0.f, 0.f};
#pragma unroll
        for (int dy = 0; dy < 3; dy++)
#pragma unroll
            for (int dx = 0; dx < 3; dx++) {
                float ww = w[dy * 3 + dx];
#pragma unroll
                for (int i = 0; i < 4; i++)
                    o[i] += ww * t[dy][i + dx];
            }

        float sc = __ldg(GG[pr] + c) * rsqrtf(__ldg(VV[pr] + c) + EPS);
        float sh = __ldg(BB[pr] + c) - __ldg(MM[pr] + c) * sc;
        float4 res;
        res.x = o[0] * sc + sh;
        res.y = o[1] * sc + sh;
        res.z = o[2] * sc + sh;
        res.w = o[3] * sc + sh;
        *(float4*)&g_y[pr][(size_t)bc * NPIX + p0] = res;
    }
}

// ---------------------------------------------------------------------------
// Kernel B (tf32 TC, double-buffered): proj GEMM, output in WINDOWED order.
// B loads gather from plain g_y via 8 precomputed pixel offsets per thread.
// ---------------------------------------------------------------------------
__global__ void __launch_bounds__(256, 2) proj_gemm_tc(
    const float* __restrict__ pw0, const float* __restrict__ pw1,
    const float* __restrict__ pw2)
{
    __shared__ uint32_t As[2][128 * 20];
    __shared__ uint32_t Bs[2][16 * 136];

    int mb = blockIdx.x;                 // 0..3
    int nb = blockIdx.y;                 // 0..24
    int bz = blockIdx.z;                 // b*3 + proj
    int pr = bz % 3, b = bz / 3;
    const float* A = (pr == 0) ? pw0 : ((pr == 1) ? pw1 : pw2);
    const float* B = g_y[pr] + (size_t)b * DIM * NPIX;

    int tid = threadIdx.x;
    int lane = tid & 31, warp = tid >> 5;
    int wm = (warp & 1) * 64;
    int wn = (warp >> 1) * 32;
    int m0 = mb * 128, n0 = nb * 128;

    int aRow0 = (tid * 2) >> 2,     aK0 = ((tid * 2) & 3) * 4;
    int aRow1 = (tid * 2 + 1) >> 2, aK1 = ((tid * 2 + 1) & 3) * 4;
    int bRow0 = (tid * 2) >> 5,     bC0 = ((tid * 2) & 31) * 4;
    int bRow1 = (tid * 2 + 1) >> 5, bC1 = ((tid * 2 + 1) & 31) * 4;

    // precompute windowed->plain offsets for the 8 B elements this thread stages
    int bo[8];
    bool bvld[8];
#pragma unroll
    for (int e = 0; e < 4; e++) {
        int n = n0 + bC0 + e;
        bvld[e] = (n < NPIX);
        bo[e] = bvld[e] ? pixoff(n) : 0;
        int n2 = n0 + bC1 + e;
        bvld[4 + e] = (n2 < NPIX);
        bo[4 + e] = bvld[4 + e] ? pixoff(n2) : 0;
    }

    float acc[4][4][4];
#pragma unroll
    for (int mt = 0; mt < 4; mt++)
#pragma unroll
        for (int nt = 0; nt < 4; nt++)
#pragma unroll
            for (int i = 0; i < 4; i++) acc[mt][nt][i] = 0.f;

    // prologue: stage 0
    {
        float4 va0 = *(const float4*)(A + (size_t)(m0 + aRow0) * DIM + aK0);
        float4 va1 = *(const float4*)(A + (size_t)(m0 + aRow1) * DIM + aK1);
        uint32_t* d0 = &As[0][aRow0 * 20 + aK0];
        d0[0] = f2tf(va0.x); d0[1] = f2tf(va0.y); d0[2] = f2tf(va0.z); d0[3] = f2tf(va0.w);
        uint32_t* d1 = &As[0][aRow1 * 20 + aK1];
        d1[0] = f2tf(va1.x); d1[1] = f2tf(va1.y); d1[2] = f2tf(va1.z); d1[3] = f2tf(va1.w);
        const float* r0 = B + (size_t)bRow0 * NPIX;
        const float* r1 = B + (size_t)bRow1 * NPIX;
        uint32_t* e0 = &Bs[0][bRow0 * 136 + bC0];
        uint32_t* e1 = &Bs[0][bRow1 * 136 + bC1];
#pragma unroll
        for (int e = 0; e < 4; e++) {
            e0[e] = f2tf(bvld[e] ? __ldg(r0 + bo[e]) : 0.f);
            e1[e] = f2tf(bvld[4 + e] ? __ldg(r1 + bo[4 + e]) : 0.f);
        }
    }
    __syncthreads();

    const int NS = DIM / 16;
    for (int s = 0; s < NS; s++) {
        float4 pa0, pa1;
        float pb[8];
        bool more = (s + 1) < NS;
        if (more) {
            int k0 = (s + 1) * 16;
            pa0 = *(const float4*)(A + (size_t)(m0 + aRow0) * DIM + k0 + aK0);
            pa1 = *(const float4*)(A + (size_t)(m0 + aRow1) * DIM + k0 + aK1);
            const float* r0 = B + (size_t)(k0 + bRow0) * NPIX;
            const float* r1 = B + (size_t)(k0 + bRow1) * NPIX;
#pragma unroll
            for (int e = 0; e < 4; e++) {
                pb[e]     = bvld[e]     ? __ldg(r0 + bo[e])     : 0.f;
                pb[4 + e] = bvld[4 + e] ? __ldg(r1 + bo[4 + e]) : 0.f;
            }
        }

        int buf = s & 1;
        const uint32_t* Ab = As[buf];
        const uint32_t* Bb = Bs[buf];
#pragma unroll
        for (int ks = 0; ks < 2; ks++) {
            int k = ks * 8;
            uint32_t af[4][4], bf[4][2];
#pragma unroll
            for (int mt = 0; mt < 4; mt++) {
                int r = wm + mt * 16 + (lane >> 2);
                int cc = k + (lane & 3);
                af[mt][0] = Ab[r * 20 + cc];
                af[mt][1] = Ab[(r + 8) * 20 + cc];
                af[mt][2] = Ab[r * 20 + cc + 4];
                af[mt][3] = Ab[(r + 8) * 20 + cc + 4];
            }
#pragma unroll
            for (int nt = 0; nt < 4; nt++) {
                int nn = wn + nt * 8 + (lane >> 2);
                bf[nt][0] = Bb[(k + (lane & 3)) * 136 + nn];
                bf[nt][1] = Bb[(k + 4 + (lane & 3)) * 136 + nn];
            }
#pragma unroll
            for (int mt = 0; mt < 4; mt++)
#pragma unroll
                for (int nt = 0; nt < 4; nt++)
                    mma_tf32(acc[mt][nt], af[mt], bf[nt]);
        }

        if (more) {
            int nbuf = (s + 1) & 1;
            uint32_t* d0 = &As[nbuf][aRow0 * 20 + aK0];
            d0[0] = f2tf(pa0.x); d0[1] = f2tf(pa0.y); d0[2] = f2tf(pa0.z); d0[3] = f2tf(pa0.w);
            uint32_t* d1 = &As[nbuf][aRow1 * 20 + aK1];
            d1[0] = f2tf(pa1.x); d1[1] = f2tf(pa1.y); d1[2] = f2tf(pa1.z); d1[3] = f2tf(pa1.w);
            uint32_t* e0 = &Bs[nbuf][bRow0 * 136 + bC0];
            uint32_t* e1 = &Bs[nbuf][bRow1 * 136 + bC1];
#pragma unroll
            for (int e = 0; e < 4; e++) {
                e0[e] = f2tf(pb[e]);
                e1[e] = f2tf(pb[4 + e]);
            }
        }
        __syncthreads();
    }

    // epilogue: g_qkv in windowed order -> plain coalesced float2
    float* Out = g_qkv[pr] + (size_t)b * INNER * NPIX;
#pragma unroll
    for (int mt = 0; mt < 4; mt++) {
#pragma unroll
        for (int rr = 0; rr < 2; rr++) {
            int m = m0 + wm + mt * 16 + (lane >> 2) + rr * 8;
#pragma unroll
            for (int nt = 0; nt < 4; nt++) {
                int n = n0 + wn + nt * 8 + (lane & 3) * 2;
                if (n < NPIX) {
                    float2 v;
                    v.x = acc[mt][nt][rr * 2 + 0];
                    v.y = acc[mt][nt][rr * 2 + 1];
                    *(float2*)&Out[(size_t)m * NPIX + n] = v;
                }
            }
        }
    }
}

// ---------------------------------------------------------------------------
// Kernel E (tf32 TC, double-buffered): out GEMM. B = g_att (windowed, linear).
// Epilogue un-permutes: scalar stores at precomputed pixel offsets.
// ---------------------------------------------------------------------------
__global__ void __launch_bounds__(256, 2) out_gemm_tc(
    const float* __restrict__ A, const float* __restrict__ ob,
    float* __restrict__ out)
{
    __shared__ uint32_t As[2][128 * 20];
    __shared__ uint32_t Bs[2][16 * 136];

    int mb = blockIdx.x;                 // 0..1
    int nb = blockIdx.y;                 // 0..24
    int b  = blockIdx.z;                 // 0..15
    const float* B = g_att + (size_t)b * INNER * NPIX;

    int tid = threadIdx.x;
    int lane = tid & 31, warp = tid >> 5;
    int wm = (warp & 1) * 64;
    int wn = (warp >> 1) * 32;
    int m0 = mb * 128, n0 = nb * 128;

    int aRow0 = (tid * 2) >> 2,     aK0 = ((tid * 2) & 3) * 4;
    int aRow1 = (tid * 2 + 1) >> 2, aK1 = ((tid * 2 + 1) & 3) * 4;
    int bRow0 = (tid * 2) >> 5,     bC0 = ((tid * 2) & 31) * 4;
    int bRow1 = (tid * 2 + 1) >> 5, bC1 = ((tid * 2 + 1) & 31) * 4;
    bool bOk0 = (n0 + bC0) < NPIX, bOk1 = (n0 + bC1) < NPIX;

    // epilogue un-permute offsets (8 per thread)
    int eo[8];
    bool evld[8];
#pragma unroll
    for (int nt = 0; nt < 4; nt++)
#pragma unroll
        for (int c = 0; c < 2; c++) {
            int id = nt * 2 + c;
            int n = n0 + wn + nt * 8 + (lane & 3) * 2 + c;
            evld[id] = (n < NPIX);
            eo[id] = evld[id] ? pixoff(n) : 0;
        }

    float acc[4][4][4];
#pragma unroll
    for (int mt = 0; mt < 4; mt++)
#pragma unroll
        for (int nt = 0; nt < 4; nt++)
#pragma unroll
            for (int i = 0; i < 4; i++) acc[mt][nt][i] = 0.f;

    {
        float4 va0 = *(const float4*)(A + (size_t)(m0 + aRow0) * INNER + aK0);
        float4 va1 = *(const float4*)(A + (size_t)(m0 + aRow1) * INNER + aK1);
        uint32_t* d0 = &As[0][aRow0 * 20 + aK0];
        d0[0] = f2tf(va0.x); d0[1] = f2tf(va0.y); d0[2] = f2tf(va0.z); d0[3] = f2tf(va0.w);
        uint32_t* d1 = &As[0][aRow1 * 20 + aK1];
        d1[0] = f2tf(va1.x); d1[1] = f2tf(va1.y); d1[2] = f2tf(va1.z); d1[3] = f2tf(va1.w);
        float4 vb0 = make_float4(0.f, 0.f, 0.f, 0.f), vb1 = vb0;
        if (bOk0) vb0 = *(const float4*)(B + (size_t)bRow0 * NPIX + n0 + bC0);
        if (bOk1) vb1 = *(const float4*)(B + (size_t)bRow1 * NPIX + n0 + bC1);
        uint32_t* e0 = &Bs[0][bRow0 * 136 + bC0];
        e0[0] = f2tf(vb0.x); e0[1] = f2tf(vb0.y); e0[2] = f2tf(vb0.z); e0[3] = f2tf(vb0.w);
        uint32_t* e1 = &Bs[0][bRow1 * 136 + bC1];
        e1[0] = f2tf(vb1.x); e1[1] = f2tf(vb1.y); e1[2] = f2tf(vb1.z); e1[3] = f2tf(vb1.w);
    }
    __syncthreads();

    const int NS = INNER / 16;
    for (int s = 0; s < NS; s++) {
        float4 pa0, pa1, pb0, pb1;
        bool more = (s + 1) < NS;
        if (more) {
            int k0 = (s + 1) * 16;
            pa0 = *(const float4*)(A + (size_t)(m0 + aRow0) * INNER + k0 + aK0);
            pa1 = *(const float4*)(A + (size_t)(m0 + aRow1) * INNER + k0 + aK1);
            pb0 = pb1 = make_float4(0.f, 0.f, 0.f, 0.f);
            if (bOk0) pb0 = *(const float4*)(B + (size_t)(k0 + bRow0) * NPIX + n0 + bC0);
            if (bOk1) pb1 = *(const float4*)(B + (size_t)(k0 + bRow1) * NPIX + n0 + bC1);
        }

        int buf = s & 1;
        const uint32_t* Ab = As[buf];
        const uint32_t* Bb = Bs[buf];
#pragma unroll
        for (int ks = 0; ks < 2; ks++) {
            int k = ks * 8;
            uint32_t af[4][4], bf[4][2];
#pragma unroll
            for (int mt = 0; mt < 4; mt++) {
                int r = wm + mt * 16 + (lane >> 2);
                int cc = k + (lane & 3);
                af[mt][0] = Ab[r * 20 + cc];
                af[mt][1] = Ab[(r + 8) * 20 + cc];
                af[mt][2] = Ab[r * 20 + cc + 4];
                af[mt][3] = Ab[(r + 8) * 20 + cc + 4];
            }
#pragma unroll
            for (int nt = 0; nt < 4; nt++) {
                int nn = wn + nt * 8 + (lane >> 2);
                bf[nt][0] = Bb[(k + (lane & 3)) * 136 + nn];
                bf[nt][1] = Bb[(k + 4 + (lane & 3)) * 136 + nn];
            }
#pragma unroll
            for (int mt = 0; mt < 4; mt++)
#pragma unroll
                for (int nt = 0; nt < 4; nt++)
                    mma_tf32(acc[mt][nt], af[mt], bf[nt]);
        }

        if (more) {
            int nbuf = (s + 1) & 1;
            uint32_t* d0 = &As[nbuf][aRow0 * 20 + aK0];
            d0[0] = f2tf(pa0.x); d0[1] = f2tf(pa0.y); d0[2] = f2tf(pa0.z); d0[3] = f2tf(pa0.w);
            uint32_t* d1 = &As[nbuf][aRow1 * 20 + aK1];
            d1[0] = f2tf(pa1.x); d1[1] = f2tf(pa1.y); d1[2] = f2tf(pa1.z); d1[3] = f2tf(pa1.w);
            uint32_t* e0 = &Bs[nbuf][bRow0 * 136 + bC0];
            e0[0] = f2tf(pb0.x); e0[1] = f2tf(pb0.y); e0[2] = f2tf(pb0.z); e0[3] = f2tf(pb0.w);
            uint32_t* e1 = &Bs[nbuf][bRow1 * 136 + bC1];
            e1[0] = f2tf(pb1.x); e1[1] = f2tf(pb1.y); e1[2] = f2tf(pb1.z); e1[3] = f2tf(pb1.w);
        }
        __syncthreads();
    }

    // epilogue: un-permute to plain [b][co][y][x]
#pragma unroll
    for (int mt = 0; mt < 4; mt++) {
#pragma unroll
        for (int rr = 0; rr < 2; rr++) {
            int m = m0 + wm + mt * 16 + (lane >> 2) + rr * 8;
            float bias = __ldg(ob + m);
            float* Orow = out + (size_t)(b * DIM + m) * NPIX;
#pragma unroll
            for (int nt = 0; nt < 4; nt++) {
#pragma unroll
                for (int c = 0; c < 2; c++) {
                    int id = nt * 2 + c;
                    if (evld[id])
                        Orow[eo[id]] = acc[mt][nt][rr * 2 + c] + bias;
                }
            }
        }
    }
}

// ---------------------------------------------------------------------------
// Kernel D (tf32 TC): windowed attention. One CTA per (b, h, w).
// Gather and store are now CONTIGUOUS (windowed layout): token base w*49.
// ---------------------------------------------------------------------------
__global__ void __launch_bounds__(256) attn_tc() {
    __shared__ uint32_t qs[64 * 68];   // Q tf32 [t][d]; later attnS (float) [i][j]
    __shared__ uint32_t ks[56 * 68];   // K tf32 [t][d]
    __shared__ uint32_t vs[64 * 60];   // V tf32 [d][t]

    int w = blockIdx.x, h = blockIdx.y, b = blockIdx.z;
    int tid = threadIdx.x, lane = tid & 31, warp = tid >> 5;
    int tb = w * NTOK;                 // contiguous token base

    size_t cbase = ((size_t)b * INNER + h * DHEAD) * NPIX;
    const float* qg = g_qkv[0] + cbase + tb;
    const float* kg = g_qkv[1] + cbase + tb;
    const float* vg = g_qkv[2] + cbase + tb;

    for (int idx = tid; idx < DHEAD * NTOK; idx += 256) {
        int d = idx / NTOK, t = idx - d * NTOK;
        size_t g = (size_t)d * NPIX + t;     // contiguous 49-float runs
        qs[t * 68 + d] = f2tf(__ldg(qg + g));
        ks[t * 68 + d] = f2tf(__ldg(kg + g));
        vs[d * 60 + t] = f2tf(__ldg(vg + g));
    }
    for (int idx = tid; idx < DHEAD * 7; idx += 256) {
        int d = idx / 7, t = NTOK + idx % 7;
        vs[d * 60 + t] = 0u;
    }
    __syncthreads();

    int wm = (warp >> 1) * 16;
    int wn = (warp & 1) * 32;
    int ntmaxQK = (warp & 1) ? 3 : 4;

    float acc[4][4];
#pragma unroll
    for (int nt = 0; nt < 4; nt++)
#pragma unroll
        for (int i = 0; i < 4; i++) acc[nt][i] = 0.f;

#pragma unroll
    for (int ks8 = 0; ks8 < 8; ks8++) {
        int k0 = ks8 * 8;
        int r = wm + (lane >> 2), kk = k0 + (lane & 3);
        uint32_t af[4];
        af[0] = qs[r * 68 + kk];
        af[1] = qs[(r + 8) * 68 + kk];
        af[2] = qs[r * 68 + kk + 4];
        af[3] = qs[(r + 8) * 68 + kk + 4];
#pragma unroll
        for (int nt = 0; nt < 4; nt++) {
            if (nt < ntmaxQK) {
                int n = wn + nt * 8 + (lane >> 2);
                uint32_t bf[2];
                bf[0] = ks[n * 68 + kk];
                bf[1] = ks[n * 68 + kk + 4];
                mma_tf32(acc[nt], af, bf);
            }
        }
    }
    __syncthreads();

    float* attnS = (float*)qs;
    const float* bptr = g_bias + h * NTOK * NTOK;
#pragma unroll
    for (int nt = 0; nt < 4; nt++) {
        if (nt < ntmaxQK) {
#pragma unroll
            for (int rr = 0; rr < 2; rr++) {
                int i = wm + (lane >> 2) + rr * 8;
                if (i < NTOK) {
#pragma unroll
                    for (int c = 0; c < 2; c++) {
                        int j = wn + nt * 8 + (lane & 3) * 2 + c;
                        if (j < NTOK)
                            attnS[i * 68 + j] = acc[nt][rr * 2 + c] * 0.125f
                                              + __ldg(bptr + i * NTOK + j);
                    }
                }
            }
        }
    }
    __syncthreads();

    {
        int qd = lane >> 2, ql = lane & 3;
        int i = warp * 8 + qd;
        bool rowOk = (i < NTOK);
        float v[14];
        float mx = -1e30f;
#pragma unroll
        for (int it = 0; it < 14; it++) {
            int j = ql + it * 4;
            v[it] = (rowOk && j < NTOK) ? attnS[i * 68 + j] : -1e30f;
            mx = fmaxf(mx, v[it]);
        }
        mx = fmaxf(mx, __shfl_xor_sync(0xffffffffu, mx, 1));
        mx = fmaxf(mx, __shfl_xor_sync(0xffffffffu, mx, 2));
        float s = 0.f;
#pragma unroll
        for (int it = 0; it < 14; it++) {
            int j = ql + it * 4;
            float e = (rowOk && j < NTOK) ? __expf(v[it] - mx) : 0.f;
            v[it] = e;
            s += e;
        }
        s += __shfl_xor_sync(0xffffffffu, s, 1);
        s += __shfl_xor_sync(0xffffffffu, s, 2);
        float inv = 1.f / s;
        if (rowOk) {
#pragma unroll
            for (int it = 0; it < 14; it++) {
                int j = ql + it * 4;
                attnS[i * 68 + j] = v[it] * inv;
            }
        }
    }
    __syncthreads();

    const uint32_t* attnU = (const uint32_t*)attnS;
    float acc2[4][4];
#pragma unroll
    for (int nt = 0; nt < 4; nt++)
#pragma unroll
        for (int i = 0; i < 4; i++) acc2[nt][i] = 0.f;

#pragma unroll
    for (int ks8 = 0; ks8 < 7; ks8++) {
        int k0 = ks8 * 8;
        int r = wm + (lane >> 2), kk = k0 + (lane & 3);
        uint32_t af[4];
        af[0] = vs[r * 60 + kk];
        af[1] = vs[(r + 8) * 60 + kk];
        af[2] = vs[r * 60 + kk + 4];
        af[3] = vs[(r + 8) * 60 + kk + 4];
#pragma unroll
        for (int nt = 0; nt < 4; nt++) {
            int n = wn + nt * 8 + (lane >> 2);
            uint32_t bf[2];
            bf[0] = (n < NTOK) ? attnU[n * 68 + kk] : 0u;
            bf[1] = (n < NTOK) ? attnU[n * 68 + kk + 4] : 0u;
            mma_tf32(acc2[nt], af, bf);
        }
    }

    // store: contiguous windowed layout [b][ci][w*49 + i]
    float* outp = g_att + (size_t)b * INNER * NPIX + (size_t)h * DHEAD * NPIX + tb;
#pragma unroll
    for (int nt = 0; nt < 4; nt++) {
#pragma unroll
        for (int c = 0; c < 2; c++) {
            int i = wn + nt * 8 + (lane & 3) * 2 + c;
            if (i < NTOK) {
#pragma unroll
                for (int rr = 0; rr < 2; rr++) {
                    int d = wm + (lane >> 2) + rr * 8;
                    outp[(size_t)d * NPIX + i] = acc2[nt][rr * 2 + c];
                }
            }
        }
    }
}

// ---------------------------------------------------------------------------
extern "C" void kernel_launch(void* const* d_in, const int* in_sizes, int n_in,
                              void* d_out, int out_size) {
    const float* x   = (const float*)d_in[0];
    const float* qdw = (const float*)d_in[1];
    const float* qg  = (const float*)d_in[2];
    const float* qb  = (const float*)d_in[3];
    const float* qm  = (const float*)d_in[4];
    const float* qv  = (const float*)d_in[5];
    const float* qpw = (const float*)d_in[6];
    const float* kdw = (const float*)d_in[7];
    const float* kg  = (const float*)d_in[8];
    const float* kb  = (const float*)d_in[9];
    const float* km  = (const float*)d_in[10];
    const float* kv  = (const float*)d_in[11];
    const float* kpw = (const float*)d_in[12];
    const float* vdw = (const float*)d_in[13];
    const float* vg  = (const float*)d_in[14];
    const float* vb  = (const float*)d_in[15];
    const float* vm  = (const float*)d_in[16];
    const float* vv  = (const float*)d_in[17];
    const float* vpw = (const float*)d_in[18];
    const float* pos = (const float*)d_in[19];
    const float* ow  = (const float*)d_in[20];
    const float* obias = (const float*)d_in[21];
    float* out = (float*)d_out;

    bias_kernel<<<(HEADS * NTOK * NTOK + 255) / 256, 256>>>(pos);

    dwbn_kernel<<<dim3((NPIX / 4 + 255) / 256, BATCH * DIM), 256>>>(
        x, qdw, qg, qb, qm, qv, kdw, kg, kb, km, kv, vdw, vg, vb, vm, vv);

    proj_gemm_tc<<<dim3(4, 25, BATCH * 3), 256>>>(qpw, kpw, vpw);

    attn_tc<<<dim3(NWIN, HEADS, BATCH), 256>>>();

    out_gemm_tc<<<dim3(2, 25, BATCH), 256>>>(ow, obias, out);
}

// round 11
// speedup vs baseline: 1.4975x; 1.0638x over previous
#include <cuda_runtime.h>
#include <cuda_fp16.h>
#include <math.h>
#include <stdint.h>

#define DIM    256
#define INNER  512
#define HEADS  8
#define DHEAD  64
#define NTOK   49
#define NPIX   3136
#define BATCH  16
#define NWIN   64
#define EPS    1e-5f

// Scratch (allocation-free). ALL intermediates fp16, WINDOWED order pix' = w*49+t.
__device__ __align__(16) __half g_y[3][BATCH * DIM * NPIX];      // dwbn out
__device__ __align__(16) __half g_qkv[3][BATCH * INNER * NPIX];  // proj out
__device__ __align__(16) __half g_att[BATCH * INNER * NPIX];     // attn out
__device__ float g_bias[HEADS * NTOK * NTOK];

// ---------------------------------------------------------------------------
// helpers
// ---------------------------------------------------------------------------
__device__ __forceinline__ void mma_f16(float c[4], const uint32_t a[4], const uint32_t b[2]) {
    asm volatile(
        "mma.sync.aligned.m16n8k16.row.col.f32.f16.f16.f32 "
        "{%0,%1,%2,%3}, {%4,%5,%6,%7}, {%8,%9}, {%0,%1,%2,%3};\n"
        : "+f"(c[0]), "+f"(c[1]), "+f"(c[2]), "+f"(c[3])
        : "r"(a[0]), "r"(a[1]), "r"(a[2]), "r"(a[3]), "r"(b[0]), "r"(b[1]));
}

__device__ __forceinline__ void ldsm4(uint32_t r[4], uint32_t addr) {
    asm volatile("ldmatrix.sync.aligned.m8n8.x4.shared.b16 {%0,%1,%2,%3}, [%4];"
        : "=r"(r[0]), "=r"(r[1]), "=r"(r[2]), "=r"(r[3]) : "r"(addr));
}

__device__ __forceinline__ void ldsm4t(uint32_t r[4], uint32_t addr) {
    asm volatile("ldmatrix.sync.aligned.m8n8.x4.trans.shared.b16 {%0,%1,%2,%3}, [%4];"
        : "=r"(r[0]), "=r"(r[1]), "=r"(r[2]), "=r"(r[3]) : "r"(addr));
}

__device__ __forceinline__ uint32_t sptr(const void* p) {
    return (uint32_t)__cvta_generic_to_shared(p);
}

__device__ __forceinline__ uint32_t pack2(float a, float b) {
    __half2 h = __floats2half2_rn(a, b);
    return *reinterpret_cast<uint32_t*>(&h);
}

// windowed index -> plain pixel offset
__device__ __forceinline__ int pixoff(int n) {
    int w = n / 49, t = n - w * 49;
    int ty = t / 7, tx = t - ty * 7;
    return ((w >> 3) * 7 + ty) * 56 + (w & 7) * 7 + tx;
}

// ---------------------------------------------------------------------------
// Kernel C: relative position bias [h][i][j]
// ---------------------------------------------------------------------------
__global__ void bias_kernel(const float* __restrict__ pos) {
    int idx = blockIdx.x * 256 + threadIdx.x;
    if (idx >= HEADS * NTOK * NTOK) return;
    int h = idx / (NTOK * NTOK);
    int r = idx % (NTOK * NTOK);
    int i = r / NTOK, j = r % NTOK;
    int xi = i / 7, yi = i % 7, xj = j / 7, yj = j % 7;
    int rel = (xj - xi + 6) * 13 + (yj - yi + 6);
    g_bias[idx] = __ldg(pos + rel * HEADS + h);
}

// ---------------------------------------------------------------------------
// Kernel A: dwconv3x3 + BN, 4 row-aligned pixels/thread; fp16 WINDOWED stores.
// ---------------------------------------------------------------------------
__global__ void __launch_bounds__(256) dwbn_kernel(
    const float* __restrict__ x,
    const float* __restrict__ dwq, const float* __restrict__ gq, const float* __restrict__ bq,
    const float* __restrict__ mq,  const float* __restrict__ vq,
    const float* __restrict__ dwk, const float* __restrict__ gk, const float* __restrict__ bk,
    const float* __restrict__ mk,  const float* __restrict__ vk,
    const float* __restrict__ dwv, const float* __restrict__ gv, const float* __restrict__ bv,
    const float* __restrict__ mv,  const float* __restrict__ vv)
{
    int pg = blockIdx.x * 256 + threadIdx.x;
    if (pg >= NPIX / 4) return;
    int p0 = pg * 4;
    int bc = blockIdx.y;
    int c  = bc & (DIM - 1);
    const float* xp = x + (size_t)bc * NPIX;
    int y0 = p0 / 56, x0 = p0 % 56;

    float t[3][6];
#pragma unroll
    for (int dy = 0; dy < 3; dy++) {
        int yy = y0 + dy - 1;
        bool rowOk = (yy >= 0 && yy < 56);
        const float* rp = xp + yy * 56;
        t[dy][0] = (rowOk && x0 > 0) ? __ldg(rp + x0 - 1) : 0.f;
        if (rowOk) {
            float4 mid = *(const float4*)(rp + x0);
            t[dy][1] = mid.x; t[dy][2] = mid.y; t[dy][3] = mid.z; t[dy][4] = mid.w;
        } else {
            t[dy][1] = t[dy][2] = t[dy][3] = t[dy][4] = 0.f;
        }
        t[dy][5] = (rowOk && x0 + 4 < 56) ? __ldg(rp + x0 + 4) : 0.f;
    }

    int wy = y0 / 7, ty = y0 % 7;
    int woff[4];
#pragma unroll
    for (int i = 0; i < 4; i++) {
        int xx = x0 + i;
        woff[i] = (wy * 8 + xx / 7) * 49 + ty * 7 + xx % 7;
    }

    const float* DW[3] = {dwq, dwk, dwv};
    const float* GG[3] = {gq, gk, gv};
    const float* BB[3] = {bq, bk, bv};
    const float* MM[3] = {mq, mk, mv};
    const float* VV[3] = {vq, vk, vv};

#pragma unroll
    for (int pr = 0; pr < 3; pr++) {
        const float* wp = DW[pr] + c * 9;
        float w[9];
#pragma unroll
        for (int j = 0; j < 9; j++) w[j] = __ldg(wp + j);

        float o[4] = {0.f, 0.f, 0.f, 0.f};
#pragma unroll
        for (int dy = 0; dy < 3; dy++)
#pragma unroll
            for (int dx = 0; dx < 3; dx++) {
                float ww = w[dy * 3 + dx];
#pragma unroll
                for (int i = 0; i < 4; i++)
                    o[i] += ww * t[dy][i + dx];
            }

        float sc = __ldg(GG[pr] + c) * rsqrtf(__ldg(VV[pr] + c) + EPS);
        float sh = __ldg(BB[pr] + c) - __ldg(MM[pr] + c) * sc;
        __half* dst = &g_y[pr][(size_t)bc * NPIX];
#pragma unroll
        for (int i = 0; i < 4; i++)
            dst[woff[i]] = __float2half_rn(o[i] * sc + sh);
    }
}

// ---------------------------------------------------------------------------
// fp16 GEMM core (m16n8k16 + ldmatrix): D[128,128] = A[128,K]f32 * B[K,128]f16
// BK=32, double-buffered. A smem [m][k] stride 40h, fragments via ldsm4.
// B smem [k][n] stride 136h (coalesced uint4 staging), fragments via ldsm4.TRANS
// (rows = k <= 31, in-bounds; banks 4k -> conflict-free).
// 8 warps: wmb=(warp&1)*64, wnb=(warp>>1)*32.
// ---------------------------------------------------------------------------
template<int KDIM, bool OUTHALF>
__device__ __forceinline__ void h_gemm(
    const float* __restrict__ A, int m0,
    const __half* __restrict__ B, int n0,
    void* __restrict__ OutBase,
    const float* __restrict__ biasv,
    float* __restrict__ outPlain, int bOut)
{
    __shared__ __align__(16) __half As[2][128 * 40];
    __shared__ __align__(16) __half Bs[2][32 * 136];

    int tid = threadIdx.x, lane = tid & 31, warp = tid >> 5;
    int wmb = (warp & 1) * 64, wnb = (warp >> 1) * 32;

    int am = tid >> 1, aoct = (tid & 1) * 16;     // A staging: row, k-base
    int bk = tid >> 3, bn = (tid & 7) * 16;       // B staging: k-row, n-base
    bool bOk0 = (n0 + bn) < NPIX;
    bool bOk1 = (n0 + bn + 8) < NPIX;

    // A fragment lane coords (non-trans x4: m8x2 x k8x2)
    int a_r  = (lane & 7) + ((lane >> 3) & 1) * 8;
    int a_k8 = (lane >> 4) * 8;
    // B fragment lane coords (TRANS x4 on [k][n]: k8x2 x n8x2)
    int bt_k = (lane & 7) + ((lane >> 3) & 1) * 8;
    int bt_n = (lane >> 4) * 8;

    float acc[4][4][4];
#pragma unroll
    for (int mt = 0; mt < 4; mt++)
#pragma unroll
        for (int nt = 0; nt < 4; nt++)
#pragma unroll
            for (int i = 0; i < 4; i++) acc[mt][nt][i] = 0.f;

    // prologue: stage 0
    {
        const float* ap = A + (size_t)(m0 + am) * KDIM + aoct;
        float4 f0 = *(const float4*)ap;
        float4 f1 = *(const float4*)(ap + 4);
        float4 f2 = *(const float4*)(ap + 8);
        float4 f3 = *(const float4*)(ap + 12);
        uint4 u0, u1;
        u0.x = pack2(f0.x, f0.y); u0.y = pack2(f0.z, f0.w);
        u0.z = pack2(f1.x, f1.y); u0.w = pack2(f1.z, f1.w);
        u1.x = pack2(f2.x, f2.y); u1.y = pack2(f2.z, f2.w);
        u1.z = pack2(f3.x, f3.y); u1.w = pack2(f3.z, f3.w);
        *(uint4*)&As[0][am * 40 + aoct]     = u0;
        *(uint4*)&As[0][am * 40 + aoct + 8] = u1;

        const __half* bp = B + (size_t)bk * NPIX + n0 + bn;
        uint4 v0 = make_uint4(0, 0, 0, 0), v1 = v0;
        if (bOk0) v0 = *(const uint4*)bp;
        if (bOk1) v1 = *(const uint4*)(bp + 8);
        *(uint4*)&Bs[0][bk * 136 + bn]     = v0;
        *(uint4*)&Bs[0][bk * 136 + bn + 8] = v1;
    }
    __syncthreads();

    const int NS = KDIM / 32;
    for (int s = 0; s < NS; s++) {
        uint32_t pa[8];
        uint4 pb0 = make_uint4(0, 0, 0, 0), pb1 = pb0;
        bool more = (s + 1) < NS;
        if (more) {
            int k0 = (s + 1) * 32;
            const float* ap = A + (size_t)(m0 + am) * KDIM + k0 + aoct;
            float4 f0 = *(const float4*)ap;
            float4 f1 = *(const float4*)(ap + 4);
            float4 f2 = *(const float4*)(ap + 8);
            float4 f3 = *(const float4*)(ap + 12);
            pa[0] = pack2(f0.x, f0.y); pa[1] = pack2(f0.z, f0.w);
            pa[2] = pack2(f1.x, f1.y); pa[3] = pack2(f1.z, f1.w);
            pa[4] = pack2(f2.x, f2.y); pa[5] = pack2(f2.z, f2.w);
            pa[6] = pack2(f3.x, f3.y); pa[7] = pack2(f3.z, f3.w);
            const __half* bp = B + (size_t)(k0 + bk) * NPIX + n0 + bn;
            if (bOk0) pb0 = *(const uint4*)bp;
            if (bOk1) pb1 = *(const uint4*)(bp + 8);
        }

        int buf = s & 1;
        uint32_t abase = sptr(As[buf]);
        uint32_t bbase = sptr(Bs[buf]);
#pragma unroll
        for (int ks = 0; ks < 2; ks++) {
            uint32_t af[4][4], bf[2][4];
#pragma unroll
            for (int mt = 0; mt < 4; mt++)
                ldsm4(af[mt], abase + (uint32_t)(((wmb + mt * 16 + a_r) * 40 + a_k8 + ks * 16) * 2));
#pragma unroll
            for (int p = 0; p < 2; p++)
                ldsm4t(bf[p], bbase + (uint32_t)(((ks * 16 + bt_k) * 136 + wnb + p * 16 + bt_n) * 2));
#pragma unroll
            for (int mt = 0; mt < 4; mt++)
#pragma unroll
                for (int nt = 0; nt < 4; nt++)
                    mma_f16(acc[mt][nt], af[mt], &bf[nt >> 1][(nt & 1) * 2]);
        }

        if (more) {
            int nbuf = (s + 1) & 1;
            uint4 u0, u1;
            u0.x = pa[0]; u0.y = pa[1]; u0.z = pa[2]; u0.w = pa[3];
            u1.x = pa[4]; u1.y = pa[5]; u1.z = pa[6]; u1.w = pa[7];
            *(uint4*)&As[nbuf][am * 40 + aoct]     = u0;
            *(uint4*)&As[nbuf][am * 40 + aoct + 8] = u1;
            *(uint4*)&Bs[nbuf][bk * 136 + bn]     = pb0;
            *(uint4*)&Bs[nbuf][bk * 136 + bn + 8] = pb1;
        }
        __syncthreads();
    }

    // epilogue
    if constexpr (OUTHALF) {
        __half* Out = (__half*)OutBase;
#pragma unroll
        for (int mt = 0; mt < 4; mt++) {
#pragma unroll
            for (int rr = 0; rr < 2; rr++) {
                int m = m0 + wmb + mt * 16 + (lane >> 2) + rr * 8;
#pragma unroll
                for (int nt = 0; nt < 4; nt++) {
                    int n = n0 + wnb + nt * 8 + (lane & 3) * 2;
                    if (n < NPIX) {
                        __half2 hv = __floats2half2_rn(acc[mt][nt][rr * 2 + 0],
                                                       acc[mt][nt][rr * 2 + 1]);
                        *reinterpret_cast<__half2*>(&Out[(size_t)m * NPIX + n]) = hv;
                    }
                }
            }
        }
    } else {
        int eo[8]; bool evld[8];
#pragma unroll
        for (int nt = 0; nt < 4; nt++)
#pragma unroll
            for (int c = 0; c < 2; c++) {
                int id = nt * 2 + c;
                int n = n0 + wnb + nt * 8 + (lane & 3) * 2 + c;
                evld[id] = (n < NPIX);
                eo[id] = evld[id] ? pixoff(n) : 0;
            }
#pragma unroll
        for (int mt = 0; mt < 4; mt++) {
#pragma unroll
            for (int rr = 0; rr < 2; rr++) {
                int m = m0 + wmb + mt * 16 + (lane >> 2) + rr * 8;
                float bias = __ldg(biasv + m);
                float* Orow = outPlain + (size_t)(bOut * DIM + m) * NPIX;
#pragma unroll
                for (int nt = 0; nt < 4; nt++)
#pragma unroll
                    for (int c = 0; c < 2; c++) {
                        int id = nt * 2 + c;
                        if (evld[id])
                            Orow[eo[id]] = acc[mt][nt][rr * 2 + c] + bias;
                    }
            }
        }
    }
}

// Kernel B: proj GEMM (fp16 windowed out)
__global__ void __launch_bounds__(256, 2) proj_gemm_h(
    const float* __restrict__ pw0, const float* __restrict__ pw1,
    const float* __restrict__ pw2)
{
    int mb = blockIdx.x;                 // 0..3 (fastest: L2 B reuse)
    int nb = blockIdx.y;                 // 0..24
    int bz = blockIdx.z;                 // b*3 + proj
    int pr = bz % 3, b = bz / 3;
    const float* A = (pr == 0) ? pw0 : ((pr == 1) ? pw1 : pw2);
    const __half* B = g_y[pr] + (size_t)b * DIM * NPIX;
    __half* Out = g_qkv[pr] + (size_t)b * INNER * NPIX;
    h_gemm<DIM, true>(A, mb * 128, B, nb * 128, Out, nullptr, nullptr, 0);
}

// Kernel E: out GEMM (fp32 plain out + bias, de-window scatter)
__global__ void __launch_bounds__(256, 2) out_gemm_h(
    const float* __restrict__ A, const float* __restrict__ ob,
    float* __restrict__ out)
{
    int mb = blockIdx.x;                 // 0..1
    int nb = blockIdx.y;                 // 0..24
    int b  = blockIdx.z;                 // 0..15
    const __half* B = g_att + (size_t)b * INNER * NPIX;
    h_gemm<INNER, false>(A, mb * 128, B, nb * 128, nullptr, ob, out, b);
}

// ---------------------------------------------------------------------------
// Kernel D: fp16 windowed attention (ldmatrix + m16n8k16). Operands are all
// [n][k]-shaped in smem -> non-trans ldsm everywhere. 27.6 KB smem.
// ---------------------------------------------------------------------------
__global__ void __launch_bounds__(256) attn_h() {
    __shared__ __align__(16) __half qk[2 * 64 * 72];   // Q -> dots/attnB; +64*72: K
    __shared__ __align__(16) __half vs[64 * 72];

    int w = blockIdx.x, h = blockIdx.y, b = blockIdx.z;
    int tid = threadIdx.x, lane = tid & 31, warp = tid >> 5;
    size_t cbase = ((size_t)b * INNER + h * DHEAD) * NPIX + (size_t)w * NTOK;
    const __half* qg = g_qkv[0] + cbase;
    const __half* kg = g_qkv[1] + cbase;
    const __half* vg = g_qkv[2] + cbase;

    for (int idx = tid; idx < DHEAD * NTOK; idx += 256) {
        int d = idx / NTOK, t = idx - d * NTOK;
        size_t g = (size_t)d * NPIX + t;             // contiguous 49-half runs
        qk[t * 72 + d] = __ldg(qg + g);
        qk[64 * 72 + t * 72 + d] = __ldg(kg + g);
        vs[d * 72 + t] = __ldg(vg + g);
    }
    for (int idx = tid; idx < DHEAD * 15; idx += 256) {   // zero V pads t=49..63
        int d = idx / 15, t = NTOK + idx % 15;
        vs[d * 72 + t] = __ushort_as_half((unsigned short)0);
    }
    __syncthreads();

    int wm = (warp >> 1) * 16, wn = (warp & 1) * 32;
    int a_r  = (lane & 7) + ((lane >> 3) & 1) * 8;
    int a_k8 = (lane >> 4) * 8;
    int b_r  = (lane & 7) + (lane >> 4) * 8;
    int b_k8 = ((lane >> 3) & 1) * 8;

    uint32_t qbase = sptr(qk);
    uint32_t kbase = sptr(qk + 64 * 72);
    uint32_t vbase = sptr(vs);

    // ---- QK^T (K=64: 4 k16 steps). Rows >=49 garbage, guarded at dots write.
    float acc[4][4];
#pragma unroll
    for (int nt = 0; nt < 4; nt++)
#pragma unroll
        for (int i = 0; i < 4; i++) acc[nt][i] = 0.f;

#pragma unroll
    for (int ks = 0; ks < 4; ks++) {
        uint32_t af[4], bf[2][4];
        ldsm4(af, qbase + (uint32_t)(((wm + a_r) * 72 + a_k8 + ks * 16) * 2));
#pragma unroll
        for (int p = 0; p < 2; p++)
            ldsm4(bf[p], kbase + (uint32_t)(((wn + p * 16 + b_r) * 72 + b_k8 + ks * 16) * 2));
#pragma unroll
        for (int nt = 0; nt < 4; nt++)
            mma_f16(acc[nt], af, &bf[nt >> 1][(nt & 1) * 2]);
    }
    __syncthreads();

    // ---- dots fp32 (stride 68) over qk region, +bias
    float* dots = (float*)qk;
    const float* bptr = g_bias + h * NTOK * NTOK;
#pragma unroll
    for (int nt = 0; nt < 4; nt++) {
        int col = wn + nt * 8 + (lane & 3) * 2;
#pragma unroll
        for (int rr = 0; rr < 2; rr++) {
            int i = wm + (lane >> 2) + rr * 8;
            if (i < NTOK) {
                if (col < NTOK)
                    dots[i * 68 + col] = acc[nt][rr * 2] * 0.125f + __ldg(bptr + i * NTOK + col);
                if (col + 1 < NTOK)
                    dots[i * 68 + col + 1] = acc[nt][rr * 2 + 1] * 0.125f + __ldg(bptr + i * NTOK + col + 1);
            }
        }
    }
    __syncthreads();

    // ---- softmax: quad per row (all lanes in shuffles)
    {
        int ql = lane & 3, rb = lane >> 2;
        int i = warp * 8 + rb;           // 0..63
        bool rowOk = (i < NTOK);
        float v[13];
        float mx = -1e30f;
#pragma unroll
        for (int it = 0; it < 13; it++) {
            int j = ql + it * 4;
            v[it] = (rowOk && j < NTOK) ? dots[i * 68 + j] : -1e30f;
            mx = fmaxf(mx, v[it]);
        }
        mx = fmaxf(mx, __shfl_xor_sync(0xffffffffu, mx, 1));
        mx = fmaxf(mx, __shfl_xor_sync(0xffffffffu, mx, 2));
        float s = 0.f;
#pragma unroll
        for (int it = 0; it < 13; it++) {
            int j = ql + it * 4;
            float e = (rowOk && j < NTOK) ? __expf(v[it] - mx) : 0.f;
            v[it] = e;
            s += e;
        }
        s += __shfl_xor_sync(0xffffffffu, s, 1);
        s += __shfl_xor_sync(0xffffffffu, s, 2);
        float inv = 1.f / s;
        __syncthreads();                 // all dots reads done before fp16 overwrite
        __half* aB = qk;                 // attnB [i][j] stride 72, FULL 64x64
#pragma unroll
        for (int it = 0; it < 16; it++) {
            int j = ql + it * 4;
            float val = (rowOk && it < 13 && j < NTOK) ? v[it] * inv : 0.f;
            aB[i * 72 + j] = __float2half_rn(val);
        }
    }
    __syncthreads();

    // ---- AV: outT[d][i] = sum_j V[d][j] * attnB[i][j]; K=64, pads exact zeros
    float acc2[4][4];
#pragma unroll
    for (int nt = 0; nt < 4; nt++)
#pragma unroll
        for (int i = 0; i < 4; i++) acc2[nt][i] = 0.f;

#pragma unroll
    for (int ks = 0; ks < 4; ks++) {
        uint32_t af[4], bf[2][4];
        ldsm4(af, vbase + (uint32_t)(((wm + a_r) * 72 + a_k8 + ks * 16) * 2));
#pragma unroll
        for (int p = 0; p < 2; p++)
            ldsm4(bf[p], qbase + (uint32_t)(((wn + p * 16 + b_r) * 72 + b_k8 + ks * 16) * 2));
#pragma unroll
        for (int nt = 0; nt < 4; nt++)
            mma_f16(acc2[nt], af, &bf[nt >> 1][(nt & 1) * 2]);
    }

    // ---- store: contiguous windowed fp16 [b][c][w*49+i]
    __half* outp = g_att + (size_t)b * INNER * NPIX + (size_t)h * DHEAD * NPIX + (size_t)w * NTOK;
#pragma unroll
    for (int nt = 0; nt < 4; nt++) {
        int i0 = wn + nt * 8 + (lane & 3) * 2;
#pragma unroll
        for (int c = 0; c < 2; c++) {
            int i = i0 + c;
            if (i < NTOK) {
#pragma unroll
                for (int rr = 0; rr < 2; rr++) {
                    int d = wm + (lane >> 2) + rr * 8;
                    outp[(size_t)d * NPIX + i] = __float2half_rn(acc2[nt][rr * 2 + c]);
                }
            }
        }
    }
}

// ---------------------------------------------------------------------------
extern "C" void kernel_launch(void* const* d_in, const int* in_sizes, int n_in,
                              void* d_out, int out_size) {
    const float* x   = (const float*)d_in[0];
    const float* qdw = (const float*)d_in[1];
    const float* qg  = (const float*)d_in[2];
    const float* qb  = (const float*)d_in[3];
    const float* qm  = (const float*)d_in[4];
    const float* qv  = (const float*)d_in[5];
    const float* qpw = (const float*)d_in[6];
    const float* kdw = (const float*)d_in[7];
    const float* kg  = (const float*)d_in[8];
    const float* kb  = (const float*)d_in[9];
    const float* km  = (const float*)d_in[10];
    const float* kv  = (const float*)d_in[11];
    const float* kpw = (const float*)d_in[12];
    const float* vdw = (const float*)d_in[13];
    const float* vg  = (const float*)d_in[14];
    const float* vb  = (const float*)d_in[15];
    const float* vm  = (const float*)d_in[16];
    const float* vv  = (const float*)d_in[17];
    const float* vpw = (const float*)d_in[18];
    const float* pos = (const float*)d_in[19];
    const float* ow  = (const float*)d_in[20];
    const float* obias = (const float*)d_in[21];
    float* out = (float*)d_out;

    bias_kernel<<<(HEADS * NTOK * NTOK + 255) / 256, 256>>>(pos);

    dwbn_kernel<<<dim3((NPIX / 4 + 255) / 256, BATCH * DIM), 256>>>(
        x, qdw, qg, qb, qm, qv, kdw, kg, kb, km, kv, vdw, vg, vb, vm, vv);

    proj_gemm_h<<<dim3(4, 25, BATCH * 3), 256>>>(qpw, kpw, vpw);

    attn_h<<<dim3(NWIN, HEADS, BATCH), 256>>>();

    out_gemm_h<<<dim3(2, 25, BATCH), 256>>>(ow, obias, out);
}

// round 15
// speedup vs baseline: 1.6891x; 1.1280x over previous
#include <cuda_runtime.h>
#include <math.h>
#include <stdint.h>

#define DIM    256
#define INNER  512
#define HEADS  8
#define DHEAD  64
#define NTOK   49
#define NPIX   3136
#define BATCH  16
#define NWIN   64
#define EPS    1e-5f

// Scratch (allocation-free). g_y/g_qkv/g_att ALL in WINDOWED order pix' = w*49+t.
__device__ float g_y[3][BATCH * DIM * NPIX];
__device__ float g_qkv[3][BATCH * INNER * NPIX];
__device__ float g_att[BATCH * INNER * NPIX];
__device__ float g_bias[HEADS * NTOK * NTOK];

// ---------------------------------------------------------------------------
// helpers
// ---------------------------------------------------------------------------
__device__ __forceinline__ uint32_t f2tf(float f) {
    uint32_t u;
    asm("cvt.rna.tf32.f32 %0, %1;" : "=r"(u) : "f"(f));
    return u;
}

__device__ __forceinline__ void mma_tf32(float c[4], const uint32_t a[4], const uint32_t b[2]) {
    asm volatile(
        "mma.sync.aligned.m16n8k8.row.col.f32.tf32.tf32.f32 "
        "{%0,%1,%2,%3}, {%4,%5,%6,%7}, {%8,%9}, {%0,%1,%2,%3};\n"
        : "+f"(c[0]), "+f"(c[1]), "+f"(c[2]), "+f"(c[3])
        : "r"(a[0]), "r"(a[1]), "r"(a[2]), "r"(a[3]), "r"(b[0]), "r"(b[1]));
}

// windowed index -> plain pixel offset
__device__ __forceinline__ int pixoff(int n) {
    int w = n / 49, t = n - w * 49;
    int ty = t / 7, tx = t - ty * 7;
    return ((w >> 3) * 7 + ty) * 56 + (w & 7) * 7 + tx;
}

// ---------------------------------------------------------------------------
// Kernel C: relative position bias [h][i][j]
// ---------------------------------------------------------------------------
__global__ void bias_kernel(const float* __restrict__ pos) {
    int idx = blockIdx.x * 256 + threadIdx.x;
    if (idx >= HEADS * NTOK * NTOK) return;
    int h = idx / (NTOK * NTOK);
    int r = idx % (NTOK * NTOK);
    int i = r / NTOK, j = r % NTOK;
    int xi = i / 7, yi = i % 7, xj = j / 7, yj = j % 7;
    int rel = (xj - xi + 6) * 13 + (yj - yi + 6);
    g_bias[idx] = __ldg(pos + rel * HEADS + h);
}

// ---------------------------------------------------------------------------
// Kernel A: dwconv3x3 + BN, 4 row-aligned pixels/thread; WINDOWED scatter stores.
// ---------------------------------------------------------------------------
__global__ void __launch_bounds__(256) dwbn_kernel(
    const float* __restrict__ x,
    const float* __restrict__ dwq, const float* __restrict__ gq, const float* __restrict__ bq,
    const float* __restrict__ mq,  const float* __restrict__ vq,
    const float* __restrict__ dwk, const float* __restrict__ gk, const float* __restrict__ bk,
    const float* __restrict__ mk,  const float* __restrict__ vk,
    const float* __restrict__ dwv, const float* __restrict__ gv, const float* __restrict__ bv,
    const float* __restrict__ mv,  const float* __restrict__ vv)
{
    int pg = blockIdx.x * 256 + threadIdx.x;
    if (pg >= NPIX / 4) return;
    int p0 = pg * 4;
    int bc = blockIdx.y;
    int c  = bc & (DIM - 1);
    const float* xp = x + (size_t)bc * NPIX;
    int y0 = p0 / 56, x0 = p0 % 56;

    float t[3][6];
#pragma unroll
    for (int dy = 0; dy < 3; dy++) {
        int yy = y0 + dy - 1;
        bool rowOk = (yy >= 0 && yy < 56);
        const float* rp = xp + yy * 56;
        t[dy][0] = (rowOk && x0 > 0) ? __ldg(rp + x0 - 1) : 0.f;
        if (rowOk) {
            float4 mid = *(const float4*)(rp + x0);
            t[dy][1] = mid.x; t[dy][2] = mid.y; t[dy][3] = mid.z; t[dy][4] = mid.w;
        } else {
            t[dy][1] = t[dy][2] = t[dy][3] = t[dy][4] = 0.f;
        }
        t[dy][5] = (rowOk && x0 + 4 < 56) ? __ldg(rp + x0 + 4) : 0.f;
    }

    // windowed offsets for the 4 pixels (same y row)
    int wy = y0 / 7, ty = y0 % 7;
    int woff[4];
#pragma unroll
    for (int i = 0; i < 4; i++) {
        int xx = x0 + i;
        woff[i] = (wy * 8 + xx / 7) * 49 + ty * 7 + xx % 7;
    }

    const float* DW[3] = {dwq, dwk, dwv};
    const float* GG[3] = {gq, gk, gv};
    const float* BB[3] = {bq, bk, bv};
    const float* MM[3] = {mq, mk, mv};
    const float* VV[3] = {vq, vk, vv};

#pragma unroll
    for (int pr = 0; pr < 3; pr++) {
        const float* wp = DW[pr] + c * 9;
        float w[9];
#pragma unroll
        for (int j = 0; j < 9; j++) w[j] = __ldg(wp + j);

        float o[4] = {0.f, 0.f, 0.f, 0.f};
#pragma unroll
        for (int dy = 0; dy < 3; dy++)
#pragma unroll
            for (int dx = 0; dx < 3; dx++) {
                float ww = w[dy * 3 + dx];
#pragma unroll
                for (int i = 0; i < 4; i++)
                    o[i] += ww * t[dy][i + dx];
            }

        float sc = __ldg(GG[pr] + c) * rsqrtf(__ldg(VV[pr] + c) + EPS);
        float sh = __ldg(BB[pr] + c) - __ldg(MM[pr] + c) * sc;
        float* dst = &g_y[pr][(size_t)bc * NPIX];
#pragma unroll
        for (int i = 0; i < 4; i++)
            dst[woff[i]] = o[i] * sc + sh;
    }
}

// ---------------------------------------------------------------------------
// Kernel B (tf32 TC, double-buffered, R6 structure): proj GEMM.
// B linear float4 loads (windowed g_y); writes windowed g_qkv, float2.
// ---------------------------------------------------------------------------
__global__ void __launch_bounds__(256, 2) proj_gemm_tc(
    const float* __restrict__ pw0, const float* __restrict__ pw1,
    const float* __restrict__ pw2)
{
    __shared__ uint32_t As[2][128 * 20];
    __shared__ uint32_t Bs[2][16 * 136];

    int mb = blockIdx.x;                 // 0..3 (fastest: L2 B reuse)
    int nb = blockIdx.y;                 // 0..24
    int bz = blockIdx.z;                 // b*3 + proj
    int pr = bz % 3, b = bz / 3;
    const float* A = (pr == 0) ? pw0 : ((pr == 1) ? pw1 : pw2);
    const float* B = g_y[pr] + (size_t)b * DIM * NPIX;

    int tid = threadIdx.x;
    int lane = tid & 31, warp = tid >> 5;
    int wm = (warp & 1) * 64;
    int wn = (warp >> 1) * 32;
    int m0 = mb * 128, n0 = nb * 128;

    int aRow0 = (tid * 2) >> 2,     aK0 = ((tid * 2) & 3) * 4;
    int aRow1 = (tid * 2 + 1) >> 2, aK1 = ((tid * 2 + 1) & 3) * 4;
    int bRow0 = (tid * 2) >> 5,     bC0 = ((tid * 2) & 31) * 4;
    int bRow1 = (tid * 2 + 1) >> 5, bC1 = ((tid * 2 + 1) & 31) * 4;
    bool bOk0 = (n0 + bC0) < NPIX, bOk1 = (n0 + bC1) < NPIX;

    float acc[4][4][4];
#pragma unroll
    for (int mt = 0; mt < 4; mt++)
#pragma unroll
        for (int nt = 0; nt < 4; nt++)
#pragma unroll
            for (int i = 0; i < 4; i++) acc[mt][nt][i] = 0.f;

    {
        float4 va0 = *(const float4*)(A + (size_t)(m0 + aRow0) * DIM + aK0);
        float4 va1 = *(const float4*)(A + (size_t)(m0 + aRow1) * DIM + aK1);
        uint32_t* d0 = &As[0][aRow0 * 20 + aK0];
        d0[0] = f2tf(va0.x); d0[1] = f2tf(va0.y); d0[2] = f2tf(va0.z); d0[3] = f2tf(va0.w);
        uint32_t* d1 = &As[0][aRow1 * 20 + aK1];
        d1[0] = f2tf(va1.x); d1[1] = f2tf(va1.y); d1[2] = f2tf(va1.z); d1[3] = f2tf(va1.w);
        float4 vb0 = make_float4(0.f, 0.f, 0.f, 0.f), vb1 = vb0;
        if (bOk0) vb0 = *(const float4*)(B + (size_t)bRow0 * NPIX + n0 + bC0);
        if (bOk1) vb1 = *(const float4*)(B + (size_t)bRow1 * NPIX + n0 + bC1);
        uint32_t* e0 = &Bs[0][bRow0 * 136 + bC0];
        e0[0] = f2tf(vb0.x); e0[1] = f2tf(vb0.y); e0[2] = f2tf(vb0.z); e0[3] = f2tf(vb0.w);
        uint32_t* e1 = &Bs[0][bRow1 * 136 + bC1];
        e1[0] = f2tf(vb1.x); e1[1] = f2tf(vb1.y); e1[2] = f2tf(vb1.z); e1[3] = f2tf(vb1.w);
    }
    __syncthreads();

    const int NS = DIM / 16;
    for (int s = 0; s < NS; s++) {
        float4 pa0, pa1, pb0, pb1;
        bool more = (s + 1) < NS;
        if (more) {
            int k0 = (s + 1) * 16;
            pa0 = *(const float4*)(A + (size_t)(m0 + aRow0) * DIM + k0 + aK0);
            pa1 = *(const float4*)(A + (size_t)(m0 + aRow1) * DIM + k0 + aK1);
            pb0 = pb1 = make_float4(0.f, 0.f, 0.f, 0.f);
            if (bOk0) pb0 = *(const float4*)(B + (size_t)(k0 + bRow0) * NPIX + n0 + bC0);
            if (bOk1) pb1 = *(const float4*)(B + (size_t)(k0 + bRow1) * NPIX + n0 + bC1);
        }

        int buf = s & 1;
        const uint32_t* Ab = As[buf];
        const uint32_t* Bb = Bs[buf];
#pragma unroll
        for (int ks = 0; ks < 2; ks++) {
            int k = ks * 8;
            uint32_t af[4][4], bf[4][2];
#pragma unroll
            for (int mt = 0; mt < 4; mt++) {
                int r = wm + mt * 16 + (lane >> 2);
                int cc = k + (lane & 3);
                af[mt][0] = Ab[r * 20 + cc];
                af[mt][1] = Ab[(r + 8) * 20 + cc];
                af[mt][2] = Ab[r * 20 + cc + 4];
                af[mt][3] = Ab[(r + 8) * 20 + cc + 4];
            }
#pragma unroll
            for (int nt = 0; nt < 4; nt++) {
                int nn = wn + nt * 8 + (lane >> 2);
                bf[nt][0] = Bb[(k + (lane & 3)) * 136 + nn];
                bf[nt][1] = Bb[(k + 4 + (lane & 3)) * 136 + nn];
            }
#pragma unroll
            for (int mt = 0; mt < 4; mt++)
#pragma unroll
                for (int nt = 0; nt < 4; nt++)
                    mma_tf32(acc[mt][nt], af[mt], bf[nt]);
        }

        if (more) {
            int nbuf = (s + 1) & 1;
            uint32_t* d0 = &As[nbuf][aRow0 * 20 + aK0];
            d0[0] = f2tf(pa0.x); d0[1] = f2tf(pa0.y); d0[2] = f2tf(pa0.z); d0[3] = f2tf(pa0.w);
            uint32_t* d1 = &As[nbuf][aRow1 * 20 + aK1];
            d1[0] = f2tf(pa1.x); d1[1] = f2tf(pa1.y); d1[2] = f2tf(pa1.z); d1[3] = f2tf(pa1.w);
            uint32_t* e0 = &Bs[nbuf][bRow0 * 136 + bC0];
            e0[0] = f2tf(pb0.x); e0[1] = f2tf(pb0.y); e0[2] = f2tf(pb0.z); e0[3] = f2tf(pb0.w);
            uint32_t* e1 = &Bs[nbuf][bRow1 * 136 + bC1];
            e1[0] = f2tf(pb1.x); e1[1] = f2tf(pb1.y); e1[2] = f2tf(pb1.z); e1[3] = f2tf(pb1.w);
        }
        __syncthreads();
    }

    float* Out = g_qkv[pr] + (size_t)b * INNER * NPIX;
#pragma unroll
    for (int mt = 0; mt < 4; mt++) {
#pragma unroll
        for (int rr = 0; rr < 2; rr++) {
            int m = m0 + wm + mt * 16 + (lane >> 2) + rr * 8;
#pragma unroll
            for (int nt = 0; nt < 4; nt++) {
                int n = n0 + wn + nt * 8 + (lane & 3) * 2;
                if (n < NPIX) {
                    float2 v;
                    v.x = acc[mt][nt][rr * 2 + 0];
                    v.y = acc[mt][nt][rr * 2 + 1];
                    *(float2*)&Out[(size_t)m * NPIX + n] = v;
                }
            }
        }
    }
}

// ---------------------------------------------------------------------------
// Kernel E (tf32 TC, double-buffered): out GEMM. B linear (windowed g_att);
// epilogue de-windows via scatter stores (+bias).
// ---------------------------------------------------------------------------
__global__ void __launch_bounds__(256, 2) out_gemm_tc(
    const float* __restrict__ A, const float* __restrict__ ob,
    float* __restrict__ out)
{
    __shared__ uint32_t As[2][128 * 20];
    __shared__ uint32_t Bs[2][16 * 136];

    int mb = blockIdx.x;                 // 0..1
    int nb = blockIdx.y;                 // 0..24
    int b  = blockIdx.z;                 // 0..15
    const float* B = g_att + (size_t)b * INNER * NPIX;

    int tid = threadIdx.x;
    int lane = tid & 31, warp = tid >> 5;
    int wm = (warp & 1) * 64;
    int wn = (warp >> 1) * 32;
    int m0 = mb * 128, n0 = nb * 128;

    int aRow0 = (tid * 2) >> 2,     aK0 = ((tid * 2) & 3) * 4;
    int aRow1 = (tid * 2 + 1) >> 2, aK1 = ((tid * 2 + 1) & 3) * 4;
    int bRow0 = (tid * 2) >> 5,     bC0 = ((tid * 2) & 31) * 4;
    int bRow1 = (tid * 2 + 1) >> 5, bC1 = ((tid * 2 + 1) & 31) * 4;
    bool bOk0 = (n0 + bC0) < NPIX, bOk1 = (n0 + bC1) < NPIX;

    // epilogue de-window offsets
    int eo[8]; bool evld[8];
#pragma unroll
    for (int nt = 0; nt < 4; nt++)
#pragma unroll
        for (int c = 0; c < 2; c++) {
            int id = nt * 2 + c;
            int n = n0 + wn + nt * 8 + (lane & 3) * 2 + c;
            evld[id] = (n < NPIX);
            eo[id] = evld[id] ? pixoff(n) : 0;
        }

    float acc[4][4][4];
#pragma unroll
    for (int mt = 0; mt < 4; mt++)
#pragma unroll
        for (int nt = 0; nt < 4; nt++)
#pragma unroll
            for (int i = 0; i < 4; i++) acc[mt][nt][i] = 0.f;

    {
        float4 va0 = *(const float4*)(A + (size_t)(m0 + aRow0) * INNER + aK0);
        float4 va1 = *(const float4*)(A + (size_t)(m0 + aRow1) * INNER + aK1);
        uint32_t* d0 = &As[0][aRow0 * 20 + aK0];
        d0[0] = f2tf(va0.x); d0[1] = f2tf(va0.y); d0[2] = f2tf(va0.z); d0[3] = f2tf(va0.w);
        uint32_t* d1 = &As[0][aRow1 * 20 + aK1];
        d1[0] = f2tf(va1.x); d1[1] = f2tf(va1.y); d1[2] = f2tf(va1.z); d1[3] = f2tf(va1.w);
        float4 vb0 = make_float4(0.f, 0.f, 0.f, 0.f), vb1 = vb0;
        if (bOk0) vb0 = *(const float4*)(B + (size_t)bRow0 * NPIX + n0 + bC0);
        if (bOk1) vb1 = *(const float4*)(B + (size_t)bRow1 * NPIX + n0 + bC1);
        uint32_t* e0 = &Bs[0][bRow0 * 136 + bC0];
        e0[0] = f2tf(vb0.x); e0[1] = f2tf(vb0.y); e0[2] = f2tf(vb0.z); e0[3] = f2tf(vb0.w);
        uint32_t* e1 = &Bs[0][bRow1 * 136 + bC1];
        e1[0] = f2tf(vb1.x); e1[1] = f2tf(vb1.y); e1[2] = f2tf(vb1.z); e1[3] = f2tf(vb1.w);
    }
    __syncthreads();

    const int NS = INNER / 16;
    for (int s = 0; s < NS; s++) {
        float4 pa0, pa1, pb0, pb1;
        bool more = (s + 1) < NS;
        if (more) {
            int k0 = (s + 1) * 16;
            pa0 = *(const float4*)(A + (size_t)(m0 + aRow0) * INNER + k0 + aK0);
            pa1 = *(const float4*)(A + (size_t)(m0 + aRow1) * INNER + k0 + aK1);
            pb0 = pb1 = make_float4(0.f, 0.f, 0.f, 0.f);
            if (bOk0) pb0 = *(const float4*)(B + (size_t)(k0 + bRow0) * NPIX + n0 + bC0);
            if (bOk1) pb1 = *(const float4*)(B + (size_t)(k0 + bRow1) * NPIX + n0 + bC1);
        }

        int buf = s & 1;
        const uint32_t* Ab = As[buf];
        const uint32_t* Bb = Bs[buf];
#pragma unroll
        for (int ks = 0; ks < 2; ks++) {
            int k = ks * 8;
            uint32_t af[4][4], bf[4][2];
#pragma unroll
            for (int mt = 0; mt < 4; mt++) {
                int r = wm + mt * 16 + (lane >> 2);
                int cc = k + (lane & 3);
                af[mt][0] = Ab[r * 20 + cc];
                af[mt][1] = Ab[(r + 8) * 20 + cc];
                af[mt][2] = Ab[r * 20 + cc + 4];
                af[mt][3] = Ab[(r + 8) * 20 + cc + 4];
            }
#pragma unroll
            for (int nt = 0; nt < 4; nt++) {
                int nn = wn + nt * 8 + (lane >> 2);
                bf[nt][0] = Bb[(k + (lane & 3)) * 136 + nn];
                bf[nt][1] = Bb[(k + 4 + (lane & 3)) * 136 + nn];
            }
#pragma unroll
            for (int mt = 0; mt < 4; mt++)
#pragma unroll
                for (int nt = 0; nt < 4; nt++)
                    mma_tf32(acc[mt][nt], af[mt], bf[nt]);
        }

        if (more) {
            int nbuf = (s + 1) & 1;
            uint32_t* d0 = &As[nbuf][aRow0 * 20 + aK0];
            d0[0] = f2tf(pa0.x); d0[1] = f2tf(pa0.y); d0[2] = f2tf(pa0.z); d0[3] = f2tf(pa0.w);
            uint32_t* d1 = &As[nbuf][aRow1 * 20 + aK1];
            d1[0] = f2tf(pa1.x); d1[1] = f2tf(pa1.y); d1[2] = f2tf(pa1.z); d1[3] = f2tf(pa1.w);
            uint32_t* e0 = &Bs[nbuf][bRow0 * 136 + bC0];
            e0[0] = f2tf(pb0.x); e0[1] = f2tf(pb0.y); e0[2] = f2tf(pb0.z); e0[3] = f2tf(pb0.w);
            uint32_t* e1 = &Bs[nbuf][bRow1 * 136 + bC1];
            e1[0] = f2tf(pb1.x); e1[1] = f2tf(pb1.y); e1[2] = f2tf(pb1.z); e1[3] = f2tf(pb1.w);
        }
        __syncthreads();
    }

#pragma unroll
    for (int mt = 0; mt < 4; mt++) {
#pragma unroll
        for (int rr = 0; rr < 2; rr++) {
            int m = m0 + wm + mt * 16 + (lane >> 2) + rr * 8;
            float bias = __ldg(ob + m);
            float* Orow = out + (size_t)(b * DIM + m) * NPIX;
#pragma unroll
            for (int nt = 0; nt < 4; nt++)
#pragma unroll
                for (int c = 0; c < 2; c++) {
                    int id = nt * 2 + c;
                    if (evld[id])
                        Orow[eo[id]] = acc[mt][nt][rr * 2 + c] + bias;
                }
        }
    }
}

// ---------------------------------------------------------------------------
// Kernel D (tf32 TC): windowed attention, fully contiguous gather/store (R9).
// ---------------------------------------------------------------------------
__global__ void __launch_bounds__(256) attn_tc() {
    __shared__ uint32_t qs[64 * 68];   // Q tf32 [t][d]; later attnS (float) [i][j]
    __shared__ uint32_t ks[56 * 68];   // K tf32 [t][d]
    __shared__ uint32_t vs[64 * 60];   // V tf32 [d][t]

    int w = blockIdx.x, h = blockIdx.y, b = blockIdx.z;
    int tid = threadIdx.x, lane = tid & 31, warp = tid >> 5;
    int tb = w * NTOK;

    size_t cbase = ((size_t)b * INNER + h * DHEAD) * NPIX;
    const float* qg = g_qkv[0] + cbase + tb;
    const float* kg = g_qkv[1] + cbase + tb;
    const float* vg = g_qkv[2] + cbase + tb;

    for (int idx = tid; idx < DHEAD * NTOK; idx += 256) {
        int d = idx / NTOK, t = idx - d * NTOK;
        size_t g = (size_t)d * NPIX + t;
        qs[t * 68 + d] = f2tf(__ldg(qg + g));
        ks[t * 68 + d] = f2tf(__ldg(kg + g));
        vs[d * 60 + t] = f2tf(__ldg(vg + g));
    }
    for (int idx = tid; idx < DHEAD * 7; idx += 256) {
        int d = idx / 7, t = NTOK + idx % 7;
        vs[d * 60 + t] = 0u;
    }
    __syncthreads();

    int wm = (warp >> 1) * 16;
    int wn = (warp & 1) * 32;
    int ntmaxQK = (warp & 1) ? 3 : 4;

    float acc[4][4];
#pragma unroll
    for (int nt = 0; nt < 4; nt++)
#pragma unroll
        for (int i = 0; i < 4; i++) acc[nt][i] = 0.f;

#pragma unroll
    for (int ks8 = 0; ks8 < 8; ks8++) {
        int k0 = ks8 * 8;
        int r = wm + (lane >> 2), kk = k0 + (lane & 3);
        uint32_t af[4];
        af[0] = qs[r * 68 + kk];
        af[1] = qs[(r + 8) * 68 + kk];
        af[2] = qs[r * 68 + kk + 4];
        af[3] = qs[(r + 8) * 68 + kk + 4];
#pragma unroll
        for (int nt = 0; nt < 4; nt++) {
            if (nt < ntmaxQK) {
                int n = wn + nt * 8 + (lane >> 2);
                uint32_t bf[2];
                bf[0] = ks[n * 68 + kk];
                bf[1] = ks[n * 68 + kk + 4];
                mma_tf32(acc[nt], af, bf);
            }
        }
    }
    __syncthreads();

    float* attnS = (float*)qs;
    const float* bptr = g_bias + h * NTOK * NTOK;
#pragma unroll
    for (int nt = 0; nt < 4; nt++) {
        if (nt < ntmaxQK) {
#pragma unroll
            for (int rr = 0; rr < 2; rr++) {
                int i = wm + (lane >> 2) + rr * 8;
                if (i < NTOK) {
#pragma unroll
                    for (int c = 0; c < 2; c++) {
                        int j = wn + nt * 8 + (lane & 3) * 2 + c;
                        if (j < NTOK)
                            attnS[i * 68 + j] = acc[nt][rr * 2 + c] * 0.125f
                                              + __ldg(bptr + i * NTOK + j);
                    }
                }
            }
        }
    }
    __syncthreads();

    {
        int qd = lane >> 2, ql = lane & 3;
        int i = warp * 8 + qd;
        bool rowOk = (i < NTOK);
        float v[14];
        float mx = -1e30f;
#pragma unroll
        for (int it = 0; it < 14; it++) {
            int j = ql + it * 4;
            v[it] = (rowOk && j < NTOK) ? attnS[i * 68 + j] : -1e30f;
            mx = fmaxf(mx, v[it]);
        }
        mx = fmaxf(mx, __shfl_xor_sync(0xffffffffu, mx, 1));
        mx = fmaxf(mx, __shfl_xor_sync(0xffffffffu, mx, 2));
        float s = 0.f;
#pragma unroll
        for (int it = 0; it < 14; it++) {
            int j = ql + it * 4;
            float e = (rowOk && j < NTOK) ? __expf(v[it] - mx) : 0.f;
            v[it] = e;
            s += e;
        }
        s += __shfl_xor_sync(0xffffffffu, s, 1);
        s += __shfl_xor_sync(0xffffffffu, s, 2);
        float inv = 1.f / s;
        if (rowOk) {
#pragma unroll
            for (int it = 0; it < 14; it++) {
                int j = ql + it * 4;
                attnS[i * 68 + j] = v[it] * inv;
            }
        }
    }
    __syncthreads();

    const uint32_t* attnU = (const uint32_t*)attnS;
    float acc2[4][4];
#pragma unroll
    for (int nt = 0; nt < 4; nt++)
#pragma unroll
        for (int i = 0; i < 4; i++) acc2[nt][i] = 0.f;

#pragma unroll
    for (int ks8 = 0; ks8 < 7; ks8++) {
        int k0 = ks8 * 8;
        int r = wm + (lane >> 2), kk = k0 + (lane & 3);
        uint32_t af[4];
        af[0] = vs[r * 60 + kk];
        af[1] = vs[(r + 8) * 60 + kk];
        af[2] = vs[r * 60 + kk + 4];
        af[3] = vs[(r + 8) * 60 + kk + 4];
#pragma unroll
        for (int nt = 0; nt < 4; nt++) {
            int n = wn + nt * 8 + (lane >> 2);
            uint32_t bf[2];
            bf[0] = (n < NTOK) ? attnU[n * 68 + kk] : 0u;
            bf[1] = (n < NTOK) ? attnU[n * 68 + kk + 4] : 0u;
            mma_tf32(acc2[nt], af, bf);
        }
    }

    float* outp = g_att + (size_t)b * INNER * NPIX + (size_t)h * DHEAD * NPIX + tb;
#pragma unroll
    for (int nt = 0; nt < 4; nt++) {
#pragma unroll
        for (int c = 0; c < 2; c++) {
            int i = wn + nt * 8 + (lane & 3) * 2 + c;
            if (i < NTOK) {
#pragma unroll
                for (int rr = 0; rr < 2; rr++) {
                    int d = wm + (lane >> 2) + rr * 8;
                    outp[(size_t)d * NPIX + i] = acc2[nt][rr * 2 + c];
                }
            }
        }
    }
}

// ---------------------------------------------------------------------------
extern "C" void kernel_launch(void* const* d_in, const int* in_sizes, int n_in,
                              void* d_out, int out_size) {
    const float* x   = (const float*)d_in[0];
    const float* qdw = (const float*)d_in[1];
    const float* qg  = (const float*)d_in[2];
    const float* qb  = (const float*)d_in[3];
    const float* qm  = (const float*)d_in[4];
    const float* qv  = (const float*)d_in[5];
    const float* qpw = (const float*)d_in[6];
    const float* kdw = (const float*)d_in[7];
    const float* kg  = (const float*)d_in[8];
    const float* kb  = (const float*)d_in[9];
    const float* km  = (const float*)d_in[10];
    const float* kv  = (const float*)d_in[11];
    const float* kpw = (const float*)d_in[12];
    const float* vdw = (const float*)d_in[13];
    const float* vg  = (const float*)d_in[14];
    const float* vb  = (const float*)d_in[15];
    const float* vm  = (const float*)d_in[16];
    const float* vv  = (const float*)d_in[17];
    const float* vpw = (const float*)d_in[18];
    const float* pos = (const float*)d_in[19];
    const float* ow  = (const float*)d_in[20];
    const float* obias = (const float*)d_in[21];
    float* out = (float*)d_out;

    bias_kernel<<<(HEADS * NTOK * NTOK + 255) / 256, 256>>>(pos);

    dwbn_kernel<<<dim3((NPIX / 4 + 255) / 256, BATCH * DIM), 256>>>(
        x, qdw, qg, qb, qm, qv, kdw, kg, kb, km, kv, vdw, vg, vb, vm, vv);

    proj_gemm_tc<<<dim3(4, 25, BATCH * 3), 256>>>(qpw, kpw, vpw);

    attn_tc<<<dim3(NWIN, HEADS, BATCH), 256>>>();

    out_gemm_tc<<<dim3(2, 25, BATCH), 256>>>(ow, obias, out);
}